// round 6
// baseline (speedup 1.0000x reference)
#include <cuda_runtime.h>
#include <math.h>

// Problem constants
#define Bn   8
#define Nn   2048
#define Cin  64
#define Cout 64
#define Kn   20
#define KSn  20
#define NP   (Bn*Nn)      // 16384 points
#define XK   1504         // packed GEMM inner dim: 1280 agg + 160 g + 64 feat
#define XSTRIDE 1536      // padded row stride (float4 aligned)

// ---------------- scratch (__device__ globals, no allocation) ----------------
__device__ float g_Ft[NP*Cin];            // feature transposed [p][c]   (4 MB)
__device__ int   g_idx[NP*Kn];            // knn indices                 (1.3 MB)
__device__ float g_X[(size_t)NP*XSTRIDE]; // packed per-point vectors    (100 MB)
__device__ float g_Wt[XSTRIDE*Cout];      // packed weights [k][o]
__device__ float g_bias[Cout];
__device__ float g_out1[Cout*NP];         // pre-BN output [o][p]        (4 MB)
__device__ float g_scale[Cout];
__device__ float g_shift[Cout];

// ---------------- feature transpose: [B,C,N] -> [B*N, C] ----------------
__global__ void k_transpose(const float* __restrict__ f){
    __shared__ float tile[32][33];
    int b = blockIdx.z, c0 = blockIdx.y*32, n0 = blockIdx.x*32;
    int tx = threadIdx.x, ty = threadIdx.y;
    #pragma unroll
    for (int i=0;i<4;i++)
        tile[ty+8*i][tx] = f[b*Cin*Nn + (c0+ty+8*i)*Nn + n0+tx];
    __syncthreads();
    #pragma unroll
    for (int i=0;i<4;i++)
        g_Ft[(b*Nn + n0+ty+8*i)*Cin + c0+tx] = tile[tx][ty+8*i];
}

// ---------------- pack weights Wt[k][o] + bias ----------------
__global__ void k_prepw(const float* __restrict__ conv_w,
                        const float* __restrict__ mlp_w,
                        const float* __restrict__ mlp_b,
                        const float* __restrict__ mlp_out_w,
                        const float* __restrict__ conv_b,
                        const float* __restrict__ mlp_out_b){
    int id = blockIdx.x*blockDim.x + threadIdx.x;   // < 1536*64
    int k = id >> 6, o = id & 63;
    float v = 0.f;
    if (k < 1280){
        // k == c*20+m directly; conv_w row o, col c*KS+m
        v = conv_w[o*2560 + k];
    } else if (k < 1440){
        int e = k - 1280;
        int m = e >> 3, j = e & 7;
        const float* cw = conv_w + o*2560 + 1280 + m;   // (64+c2)*20+m
        float s = 0.f;
        if (j < 7){
            for (int c2=0;c2<64;c2++) s += mlp_w[c2*7+j]*cw[c2*20];
        } else {
            for (int c2=0;c2<64;c2++) s += mlp_b[c2]*cw[c2*20];
        }
        v = s;
    } else if (k < XK){
        v = mlp_out_w[o*64 + (k-1440)];
    }
    g_Wt[k*64 + o] = v;
    if (id < 64) g_bias[id] = conv_b[id] + mlp_out_b[id];
}

// ---------------- KNN: warp per query, min-extraction top-20 ----------------
// 64 threads (2 warps) per block; STATIC shared: 24 KB points + 2*8 KB dists.
__global__ void k_knn(const float* __restrict__ x){
    __shared__ float spx[Nn];
    __shared__ float spy[Nn];
    __shared__ float spz[Nn];
    __shared__ float sdist[2][Nn];
    int t = threadIdx.x, w = t>>5, lane = t&31;
    int b = blockIdx.y;
    const float* xb = x + b*3*Nn;
    for (int e=t; e<Nn; e+=64){
        spx[e] = xb[e]; spy[e] = xb[Nn+e]; spz[e] = xb[2*Nn+e];
    }
    __syncthreads();
    float* sd = sdist[w];

    for (int i=0;i<8;i++){
        int q = blockIdx.x*16 + w*8 + i;
        float qx = spx[q], qy = spy[q], qz = spz[q];
        float mn = 3.0e38f; int amn = 0;
        // distance phase: lane owns j = lane + 32*tt, swizzled store
        #pragma unroll 8
        for (int tt=0; tt<64; tt++){
            int j = lane + (tt<<5);
            float dx = spx[j]-qx, dy = spy[j]-qy, dz = spz[j]-qz;
            float d2 = dx*dx + dy*dy + dz*dz;
            sd[j ^ (tt & 31)] = d2;
            if (d2 < mn){ mn = d2; amn = j; }
        }
        __syncwarp();
        int myn = 0;
        for (int kk=0; kk<Kn; kk++){
            // global argmin over lane caches
            float rv = mn; int ra = amn;
            #pragma unroll
            for (int off=16; off; off>>=1){
                float ov = __shfl_down_sync(0xffffffffu, rv, off);
                int   oa = __shfl_down_sync(0xffffffffu, ra, off);
                if (ov < rv){ rv = ov; ra = oa; }
            }
            int jst = __shfl_sync(0xffffffffu, ra, 0);
            if (lane == kk) myn = jst;
            int L = jst & 31;
            if (lane == L) sd[jst ^ ((jst>>5)&31)] = 3.0e38f;
            __syncwarp();
            // all 32 lanes rescan owner L's 64 slots (2 each), conflict-free banks
            int j1 = L + (lane<<5);
            int j2 = L + ((lane+32)<<5);
            float v1 = sd[j1 ^ lane];
            float v2 = sd[j2 ^ lane];
            float nv; int na;
            if (v1 <= v2){ nv = v1; na = j1; } else { nv = v2; na = j2; }
            #pragma unroll
            for (int off=16; off; off>>=1){
                float ov = __shfl_down_sync(0xffffffffu, nv, off);
                int   oa = __shfl_down_sync(0xffffffffu, na, off);
                if (ov < nv){ nv = ov; na = oa; }
            }
            nv = __shfl_sync(0xffffffffu, nv, 0);
            na = __shfl_sync(0xffffffffu, na, 0);
            if (lane == L){ mn = nv; amn = na; }
            __syncwarp();
        }
        if (lane < Kn) g_idx[(b*Nn + q)*Kn + lane] = myn;
    }
}

// ---------------- per-point: perm + agg + g-vector, pack X row ----------------
__global__ void k_point(const float* __restrict__ x,
                        const float* __restrict__ kern,
                        const float* __restrict__ onepad){
    __shared__ int   sidx[Kn];
    __shared__ float sSelf[3];
    __shared__ float srel[Kn][3];
    __shared__ float sdst[Kn];
    __shared__ float sP[Kn][KSn];
    __shared__ float scol[KSn];
    __shared__ __align__(16) float sNF[Kn][Cin];
    __shared__ __align__(16) float sX[XSTRIDE];

    int p = blockIdx.x;
    int b = p >> 11, n = p & 2047;
    int t = threadIdx.x;

    if (t < Kn) sidx[t] = g_idx[p*Kn + t];
    if (t < 3)  sSelf[t] = x[b*3*Nn + t*Nn + n];
    __syncthreads();

    if (t < Kn){
        int j = sidx[t];
        float rx = x[b*3*Nn +        j] - sSelf[0];
        float ry = x[b*3*Nn +   Nn + j] - sSelf[1];
        float rz = x[b*3*Nn + 2*Nn + j] - sSelf[2];
        srel[t][0] = rx; srel[t][1] = ry; srel[t][2] = rz;
        sdst[t] = sqrtf(rx*rx + ry*ry + rz*rz + 1e-12f);
    }
    // gather neighbor features: float4 lanes, 16 lanes per neighbor row
    for (int e=t; e<Kn*16; e+=128){
        int k = e>>4, c4 = e&15;
        const float4* src = (const float4*)(g_Ft + (size_t)(b*Nn + sidx[k])*Cin);
        ((float4*)sNF[k])[c4] = src[c4];
    }
    // self feature row + zero pad tail
    if (t < 96) sX[1440 + t] = (t < 64) ? g_Ft[p*Cin + t] : 0.f;
    __syncthreads();

    // raw perm = relu(rel @ kernals + one_padding)
    for (int e=t; e<Kn*KSn; e+=128){
        int k = e/KSn, m = e - k*KSn;
        float s = srel[k][0]*kern[m] + srel[k][1]*kern[KSn+m]
                + srel[k][2]*kern[2*KSn+m] + onepad[e];
        sP[k][m] = fmaxf(s, 0.f);
    }
    __syncthreads();

    // double normalization over k + threshold, per column m
    if (t < KSn){
        float s1 = 0.f;
        #pragma unroll
        for (int k=0;k<Kn;k++) s1 += sP[k][t];
        float inv1 = 1.f/(s1 + 1e-6f);
        float v[Kn]; float s2 = 0.f;
        #pragma unroll
        for (int k=0;k<Kn;k++){ float u = sP[k][t]*inv1; u = u*u; v[k] = u; s2 += u; }
        float inv2 = 1.f/(s2 + 1e-6f);
        float s3 = 0.f;
        #pragma unroll
        for (int k=0;k<Kn;k++){
            float u = v[k]*inv2;
            u = (u > 0.1f) ? u : 0.f;
            sP[k][t] = u; s3 += u;
        }
        scol[t] = s3;
    }
    __syncthreads();

    // g[m][j]: x-path compressed to 8 components per m
    for (int e=t; e<160; e+=128){
        int m = e>>3, j = e&7;
        float val;
        if (j < 3) val = sSelf[j]*scol[m];
        else if (j == 7) val = scol[m];
        else if (j == 6){
            float s = 0.f;
            #pragma unroll
            for (int k=0;k<Kn;k++) s += sdst[k]*sP[k][m];
            val = s;
        } else {
            float s = 0.f;
            #pragma unroll
            for (int k=0;k<Kn;k++) s += srel[k][j-3]*sP[k][m];
            val = s;
        }
        sX[1280 + m*8 + j] = val;
    }

    // agg[c][m] = sum_k NF[k][c] * P[k][m]   (128 threads: c = t&63, m half)
    {
        int c = t & 63, mh = (t>>6)*10;
        float acc[10];
        #pragma unroll
        for (int i=0;i<10;i++) acc[i] = 0.f;
        #pragma unroll
        for (int k=0;k<Kn;k++){
            float vv = sNF[k][c];
            #pragma unroll
            for (int i=0;i<10;i++) acc[i] += vv * sP[k][mh+i];
        }
        #pragma unroll
        for (int i=0;i<10;i++) sX[c*KSn + mh + i] = acc[i];
    }
    __syncthreads();

    // vectorized flush of packed row
    float4* dst = (float4*)(g_X + (size_t)p*XSTRIDE);
    const float4* src = (const float4*)sX;
    for (int e=t; e<XSTRIDE/4; e+=128) dst[e] = src[e];
}

// ---------------- GEMM: out1[o][p] = X[p][:1504] . Wt[:1504][o] + bias ----------------
__global__ void k_gemm(){
    __shared__ float As[16][132];
    __shared__ __align__(16) float Bs[16][64];
    int t = threadIdx.x;
    int p0 = blockIdx.x * 128;
    int tx = t & 15, ty = t >> 4;
    float acc[8][4];
    #pragma unroll
    for (int i=0;i<8;i++)
        #pragma unroll
        for (int j=0;j<4;j++) acc[i][j] = 0.f;

    for (int kt=0; kt<XK; kt+=16){
        #pragma unroll
        for (int h=0; h<2; h++){
            int e = t + h*256;
            int row = e >> 2, seg = e & 3;
            float4 v = *(const float4*)(g_X + (size_t)(p0+row)*XSTRIDE + kt + seg*4);
            As[seg*4+0][row] = v.x; As[seg*4+1][row] = v.y;
            As[seg*4+2][row] = v.z; As[seg*4+3][row] = v.w;
        }
        {
            int kk = t >> 4, seg = t & 15;
            float4 wv = *(const float4*)(g_Wt + (kt+kk)*64 + seg*4);
            *(float4*)&Bs[kk][seg*4] = wv;
        }
        __syncthreads();
        #pragma unroll
        for (int k=0;k<16;k++){
            float a[8];
            #pragma unroll
            for (int i=0;i<8;i++) a[i] = As[k][ty + 16*i];
            float4 bv = *(const float4*)&Bs[k][tx*4];
            #pragma unroll
            for (int i=0;i<8;i++){
                acc[i][0] += a[i]*bv.x; acc[i][1] += a[i]*bv.y;
                acc[i][2] += a[i]*bv.z; acc[i][3] += a[i]*bv.w;
            }
        }
        __syncthreads();
    }
    #pragma unroll
    for (int j=0;j<4;j++){
        int o = tx*4 + j;
        float bb = g_bias[o];
        #pragma unroll
        for (int i=0;i<8;i++)
            g_out1[o*NP + p0 + ty + 16*i] = acc[i][j] + bb;
    }
}

// ---------------- BN statistics per channel ----------------
__global__ void k_bnstat(const float* __restrict__ gamma,
                         const float* __restrict__ beta){
    int o = blockIdx.x, t = threadIdx.x;
    const float* row = g_out1 + o*NP;
    double s = 0.0, s2 = 0.0;
    for (int i=t; i<NP; i+=256){
        double v = (double)row[i];
        s += v; s2 += v*v;
    }
    __shared__ double sh1[256], sh2[256];
    sh1[t] = s; sh2[t] = s2;
    __syncthreads();
    for (int off=128; off; off>>=1){
        if (t < off){ sh1[t] += sh1[t+off]; sh2[t] += sh2[t+off]; }
        __syncthreads();
    }
    if (t == 0){
        double mean = sh1[0] / (double)NP;
        double var  = sh2[0] / (double)NP - mean*mean;
        float sc = gamma[o] / sqrtf((float)var + 1e-5f);
        g_scale[o] = sc;
        g_shift[o] = beta[o] - (float)mean * sc;
    }
}

// ---------------- finalize: affine BN + layout [B,C,N] ----------------
__global__ void k_final(float* __restrict__ out){
    int e = blockIdx.x*blockDim.x + threadIdx.x;   // < 1048576
    int n = e & 2047;
    int o = (e >> 11) & 63;
    int b = e >> 17;
    out[e] = g_out1[o*NP + b*Nn + n] * g_scale[o] + g_shift[o];
}

// ---------------- launch ----------------
extern "C" void kernel_launch(void* const* d_in, const int* in_sizes, int n_in,
                              void* d_out, int out_size){
    (void)in_sizes; (void)n_in; (void)out_size;
    const float* x         = (const float*)d_in[0];
    const float* feature   = (const float*)d_in[1];
    const float* kernals   = (const float*)d_in[2];
    const float* one_pad   = (const float*)d_in[3];
    const float* mlp_w     = (const float*)d_in[4];
    const float* mlp_b     = (const float*)d_in[5];
    const float* conv_w    = (const float*)d_in[6];
    const float* conv_b    = (const float*)d_in[7];
    const float* mlp_out_w = (const float*)d_in[8];
    const float* mlp_out_b = (const float*)d_in[9];
    const float* bn_gamma  = (const float*)d_in[10];
    const float* bn_beta   = (const float*)d_in[11];
    float* out = (float*)d_out;

    k_transpose<<<dim3(Nn/32, Cin/32, Bn), dim3(32,8)>>>(feature);
    k_prepw<<<(XSTRIDE*Cout)/256, 256>>>(conv_w, mlp_w, mlp_b,
                                         mlp_out_w, conv_b, mlp_out_b);
    k_knn<<<dim3(Nn/16, Bn), 64>>>(x);
    k_point<<<NP, 128>>>(x, kernals, one_pad);
    k_gemm<<<NP/128, 256>>>();
    k_bnstat<<<Cout, 256>>>(bn_gamma, bn_beta);
    k_final<<<(Bn*Cout*Nn)/256, 256>>>(out);
}

// round 7
// speedup vs baseline: 1.2169x; 1.2169x over previous
#include <cuda_runtime.h>
#include <math.h>

// Problem constants
#define Bn   8
#define Nn   2048
#define Cin  64
#define Cout 64
#define Kn   20
#define KSn  20
#define NP   (Bn*Nn)      // 16384 points
#define XK   1504         // packed GEMM inner dim: 1280 agg + 160 g + 64 feat
#define XKH  752          // split-K half (47 tiles of 16)
#define XSTRIDE 1536      // padded row stride (float4 aligned)

// ---------------- scratch (__device__ globals, no allocation) ----------------
__device__ float g_Ft[NP*Cin];            // feature transposed [p][c]   (4 MB)
__device__ int   g_idx[NP*Kn];            // knn indices                 (1.3 MB)
__device__ float g_X[(size_t)NP*XSTRIDE]; // packed per-point vectors    (100 MB)
__device__ float g_Wt[XSTRIDE*Cout];      // packed weights [k][o]
__device__ float g_bias[Cout];
__device__ float g_o1a[Cout*NP];          // pre-BN output half A [o][p] (4 MB)
__device__ float g_o1b[Cout*NP];          // pre-BN output half B [o][p] (4 MB)
__device__ float g_scale[Cout];
__device__ float g_shift[Cout];

// ---------------- feature transpose: [B,C,N] -> [B*N, C] ----------------
__global__ void k_transpose(const float* __restrict__ f){
    __shared__ float tile[32][33];
    int b = blockIdx.z, c0 = blockIdx.y*32, n0 = blockIdx.x*32;
    int tx = threadIdx.x, ty = threadIdx.y;
    #pragma unroll
    for (int i=0;i<4;i++)
        tile[ty+8*i][tx] = f[b*Cin*Nn + (c0+ty+8*i)*Nn + n0+tx];
    __syncthreads();
    #pragma unroll
    for (int i=0;i<4;i++)
        g_Ft[(b*Nn + n0+ty+8*i)*Cin + c0+tx] = tile[tx][ty+8*i];
}

// ---------------- pack weights Wt[k][o] + bias ----------------
__global__ void k_prepw(const float* __restrict__ conv_w,
                        const float* __restrict__ mlp_w,
                        const float* __restrict__ mlp_b,
                        const float* __restrict__ mlp_out_w,
                        const float* __restrict__ conv_b,
                        const float* __restrict__ mlp_out_b){
    int id = blockIdx.x*blockDim.x + threadIdx.x;   // < 1536*64
    int k = id >> 6, o = id & 63;
    float v = 0.f;
    if (k < 1280){
        v = conv_w[o*2560 + k];
    } else if (k < 1440){
        int e = k - 1280;
        int m = e >> 3, j = e & 7;
        const float* cw = conv_w + o*2560 + 1280 + m;   // (64+c2)*20+m
        float s = 0.f;
        if (j < 7){
            for (int c2=0;c2<64;c2++) s += mlp_w[c2*7+j]*cw[c2*20];
        } else {
            for (int c2=0;c2<64;c2++) s += mlp_b[c2]*cw[c2*20];
        }
        v = s;
    } else if (k < XK){
        v = mlp_out_w[o*64 + (k-1440)];
    }
    g_Wt[k*64 + o] = v;
    if (id < 64) g_bias[id] = conv_b[id] + mlp_out_b[id];
}

// ---------------- KNN: warp per query, min-extraction top-20 ----------------
__global__ void k_knn(const float* __restrict__ x){
    __shared__ float spx[Nn];
    __shared__ float spy[Nn];
    __shared__ float spz[Nn];
    __shared__ float sdist[2][Nn];
    int t = threadIdx.x, w = t>>5, lane = t&31;
    int b = blockIdx.y;
    const float* xb = x + b*3*Nn;
    for (int e=t; e<Nn; e+=64){
        spx[e] = xb[e]; spy[e] = xb[Nn+e]; spz[e] = xb[2*Nn+e];
    }
    __syncthreads();
    float* sd = sdist[w];

    for (int i=0;i<8;i++){
        int q = blockIdx.x*16 + w*8 + i;
        float qx = spx[q], qy = spy[q], qz = spz[q];
        float mn = 3.0e38f; int amn = 0;
        #pragma unroll 8
        for (int tt=0; tt<64; tt++){
            int j = lane + (tt<<5);
            float dx = spx[j]-qx, dy = spy[j]-qy, dz = spz[j]-qz;
            float d2 = dx*dx + dy*dy + dz*dz;
            sd[j ^ (tt & 31)] = d2;
            if (d2 < mn){ mn = d2; amn = j; }
        }
        __syncwarp();
        int myn = 0;
        for (int kk=0; kk<Kn; kk++){
            float rv = mn; int ra = amn;
            #pragma unroll
            for (int off=16; off; off>>=1){
                float ov = __shfl_down_sync(0xffffffffu, rv, off);
                int   oa = __shfl_down_sync(0xffffffffu, ra, off);
                if (ov < rv){ rv = ov; ra = oa; }
            }
            int jst = __shfl_sync(0xffffffffu, ra, 0);
            if (lane == kk) myn = jst;
            int L = jst & 31;
            if (lane == L) sd[jst ^ ((jst>>5)&31)] = 3.0e38f;
            __syncwarp();
            int j1 = L + (lane<<5);
            int j2 = L + ((lane+32)<<5);
            float v1 = sd[j1 ^ lane];
            float v2 = sd[j2 ^ lane];
            float nv; int na;
            if (v1 <= v2){ nv = v1; na = j1; } else { nv = v2; na = j2; }
            #pragma unroll
            for (int off=16; off; off>>=1){
                float ov = __shfl_down_sync(0xffffffffu, nv, off);
                int   oa = __shfl_down_sync(0xffffffffu, na, off);
                if (ov < nv){ nv = ov; na = oa; }
            }
            nv = __shfl_sync(0xffffffffu, nv, 0);
            na = __shfl_sync(0xffffffffu, na, 0);
            if (lane == L){ mn = nv; amn = na; }
            __syncwarp();
        }
        if (lane < Kn) g_idx[(b*Nn + q)*Kn + lane] = myn;
    }
}

// ---------------- per-point: perm + agg + g-vector, pack X row ----------------
// 2 points per block, 64 threads per point. sP rows padded to 24 floats
// so the agg loop reads each k-row as 5 LDS.128 broadcasts.
__global__ void k_point(const float* __restrict__ x,
                        const float* __restrict__ kern,
                        const float* __restrict__ onepad){
    __shared__ int   sidx[2][Kn];
    __shared__ float sSelf[2][3];
    __shared__ float srel[2][Kn][3];
    __shared__ float sdst[2][Kn];
    __shared__ __align__(16) float sP[2][Kn][24];
    __shared__ float scol[2][KSn];
    __shared__ __align__(16) float sNF[2][Kn][Cin];
    __shared__ __align__(16) float sX[2][XSTRIDE];

    int t = threadIdx.x;
    int half = t >> 6, u = t & 63;
    int p = blockIdx.x*2 + half;
    int b = p >> 11, n = p & 2047;

    if (u < Kn) sidx[half][u] = g_idx[p*Kn + u];
    if (u < 3)  sSelf[half][u] = x[b*3*Nn + u*Nn + n];
    __syncthreads();

    if (u < Kn){
        int j = sidx[half][u];
        float rx = x[b*3*Nn +        j] - sSelf[half][0];
        float ry = x[b*3*Nn +   Nn + j] - sSelf[half][1];
        float rz = x[b*3*Nn + 2*Nn + j] - sSelf[half][2];
        srel[half][u][0] = rx; srel[half][u][1] = ry; srel[half][u][2] = rz;
        sdst[half][u] = sqrtf(rx*rx + ry*ry + rz*rz + 1e-12f);
    }
    // gather neighbor features: float4 lanes, 16 lanes per neighbor row
    #pragma unroll
    for (int e=u; e<Kn*16; e+=64){
        int k = e>>4, c4 = e&15;
        const float4* src = (const float4*)(g_Ft + (size_t)(b*Nn + sidx[half][k])*Cin);
        ((float4*)sNF[half][k])[c4] = src[c4];
    }
    // self feature row + zero pad tail
    sX[half][1440 + u] = g_Ft[p*Cin + u];
    if (u < 32) sX[half][1504 + u] = 0.f;
    __syncthreads();

    // raw perm = relu(rel @ kernals + one_padding)
    #pragma unroll
    for (int e=u; e<Kn*KSn; e+=64){
        int k = e/KSn, m = e - k*KSn;
        float s = srel[half][k][0]*kern[m] + srel[half][k][1]*kern[KSn+m]
                + srel[half][k][2]*kern[2*KSn+m] + onepad[e];
        sP[half][k][m] = fmaxf(s, 0.f);
    }
    __syncthreads();

    // double normalization over k + threshold, per column m
    if (u < KSn){
        float s1 = 0.f;
        #pragma unroll
        for (int k=0;k<Kn;k++) s1 += sP[half][k][u];
        float inv1 = 1.f/(s1 + 1e-6f);
        float v[Kn]; float s2 = 0.f;
        #pragma unroll
        for (int k=0;k<Kn;k++){ float q = sP[half][k][u]*inv1; q = q*q; v[k] = q; s2 += q; }
        float inv2 = 1.f/(s2 + 1e-6f);
        float s3 = 0.f;
        #pragma unroll
        for (int k=0;k<Kn;k++){
            float q = v[k]*inv2;
            q = (q > 0.1f) ? q : 0.f;
            sP[half][k][u] = q; s3 += q;
        }
        scol[half][u] = s3;
    }
    __syncthreads();

    // g[m][j]: x-path compressed to 8 components per m
    #pragma unroll
    for (int e=u; e<160; e+=64){
        int m = e>>3, j = e&7;
        float val;
        if (j < 3) val = sSelf[half][j]*scol[half][m];
        else if (j == 7) val = scol[half][m];
        else if (j == 6){
            float s = 0.f;
            #pragma unroll
            for (int k=0;k<Kn;k++) s += sdst[half][k]*sP[half][k][m];
            val = s;
        } else {
            float s = 0.f;
            #pragma unroll
            for (int k=0;k<Kn;k++) s += srel[half][k][j-3]*sP[half][k][m];
            val = s;
        }
        sX[half][1280 + m*8 + j] = val;
    }

    // agg[c][m] = sum_k NF[k][c]*P[k][m]; thread u owns channel c=u, all 20 m
    {
        float acc[20];
        #pragma unroll
        for (int i=0;i<20;i++) acc[i] = 0.f;
        #pragma unroll
        for (int k=0;k<Kn;k++){
            float vv = sNF[half][k][u];
            const float4* pr = (const float4*)sP[half][k];
            float4 q0 = pr[0], q1 = pr[1], q2 = pr[2], q3 = pr[3], q4 = pr[4];
            acc[0]+=vv*q0.x;  acc[1]+=vv*q0.y;  acc[2]+=vv*q0.z;  acc[3]+=vv*q0.w;
            acc[4]+=vv*q1.x;  acc[5]+=vv*q1.y;  acc[6]+=vv*q1.z;  acc[7]+=vv*q1.w;
            acc[8]+=vv*q2.x;  acc[9]+=vv*q2.y;  acc[10]+=vv*q2.z; acc[11]+=vv*q2.w;
            acc[12]+=vv*q3.x; acc[13]+=vv*q3.y; acc[14]+=vv*q3.z; acc[15]+=vv*q3.w;
            acc[16]+=vv*q4.x; acc[17]+=vv*q4.y; acc[18]+=vv*q4.z; acc[19]+=vv*q4.w;
        }
        float4* xr = (float4*)(sX[half] + u*KSn);   // u*20*4B is 16B-aligned (80=5*16)
        xr[0] = make_float4(acc[0],acc[1],acc[2],acc[3]);
        xr[1] = make_float4(acc[4],acc[5],acc[6],acc[7]);
        xr[2] = make_float4(acc[8],acc[9],acc[10],acc[11]);
        xr[3] = make_float4(acc[12],acc[13],acc[14],acc[15]);
        xr[4] = make_float4(acc[16],acc[17],acc[18],acc[19]);
    }
    __syncthreads();

    // vectorized flush of packed row
    float4* dst = (float4*)(g_X + (size_t)p*XSTRIDE);
    const float4* src = (const float4*)sX[half];
    #pragma unroll
    for (int e=u; e<XSTRIDE/4; e+=64) dst[e] = src[e];
}

// ---------------- GEMM (split-K=2): oX[o][p] = X[p][half] . Wt[half][o] ----------------
__global__ void __launch_bounds__(256) k_gemm(){
    __shared__ float As[16][132];
    __shared__ __align__(16) float Bs[16][64];
    int t = threadIdx.x;
    int p0 = blockIdx.x * 128;
    int h  = blockIdx.y;
    int k0 = h * XKH;
    int tx = t & 15, ty = t >> 4;
    float acc[8][4];
    #pragma unroll
    for (int i=0;i<8;i++)
        #pragma unroll
        for (int j=0;j<4;j++) acc[i][j] = 0.f;

    for (int kt=k0; kt<k0+XKH; kt+=16){
        #pragma unroll
        for (int hh=0; hh<2; hh++){
            int e = t + hh*256;
            int row = e >> 2, seg = e & 3;
            float4 v = *(const float4*)(g_X + (size_t)(p0+row)*XSTRIDE + kt + seg*4);
            As[seg*4+0][row] = v.x; As[seg*4+1][row] = v.y;
            As[seg*4+2][row] = v.z; As[seg*4+3][row] = v.w;
        }
        {
            int kk = t >> 4, seg = t & 15;
            float4 wv = *(const float4*)(g_Wt + (kt+kk)*64 + seg*4);
            *(float4*)&Bs[kk][seg*4] = wv;
        }
        __syncthreads();
        #pragma unroll
        for (int k=0;k<16;k++){
            float a[8];
            #pragma unroll
            for (int i=0;i<8;i++) a[i] = As[k][ty + 16*i];
            float4 bv = *(const float4*)&Bs[k][tx*4];
            #pragma unroll
            for (int i=0;i<8;i++){
                acc[i][0] += a[i]*bv.x; acc[i][1] += a[i]*bv.y;
                acc[i][2] += a[i]*bv.z; acc[i][3] += a[i]*bv.w;
            }
        }
        __syncthreads();
    }
    float* dst = h ? g_o1b : g_o1a;
    #pragma unroll
    for (int j=0;j<4;j++){
        int o = tx*4 + j;
        float bb = h ? 0.f : g_bias[o];
        #pragma unroll
        for (int i=0;i<8;i++)
            dst[o*NP + p0 + ty + 16*i] = acc[i][j] + bb;
    }
}

// ---------------- BN statistics per channel ----------------
__global__ void k_bnstat(const float* __restrict__ gamma,
                         const float* __restrict__ beta){
    int o = blockIdx.x, t = threadIdx.x;
    const float* ra = g_o1a + o*NP;
    const float* rb = g_o1b + o*NP;
    double s = 0.0, s2 = 0.0;
    for (int i=t; i<NP; i+=256){
        double v = (double)(ra[i] + rb[i]);
        s += v; s2 += v*v;
    }
    __shared__ double sh1[256], sh2[256];
    sh1[t] = s; sh2[t] = s2;
    __syncthreads();
    for (int off=128; off; off>>=1){
        if (t < off){ sh1[t] += sh1[t+off]; sh2[t] += sh2[t+off]; }
        __syncthreads();
    }
    if (t == 0){
        double mean = sh1[0] / (double)NP;
        double var  = sh2[0] / (double)NP - mean*mean;
        float sc = gamma[o] / sqrtf((float)var + 1e-5f);
        g_scale[o] = sc;
        g_shift[o] = beta[o] - (float)mean * sc;
    }
}

// ---------------- finalize: affine BN + layout [B,C,N] ----------------
__global__ void k_final(float* __restrict__ out){
    int e = blockIdx.x*blockDim.x + threadIdx.x;   // < 1048576
    int n = e & 2047;
    int o = (e >> 11) & 63;
    int b = e >> 17;
    int idx = o*NP + b*Nn + n;
    out[e] = (g_o1a[idx] + g_o1b[idx]) * g_scale[o] + g_shift[o];
}

// ---------------- launch ----------------
extern "C" void kernel_launch(void* const* d_in, const int* in_sizes, int n_in,
                              void* d_out, int out_size){
    (void)in_sizes; (void)n_in; (void)out_size;
    const float* x         = (const float*)d_in[0];
    const float* feature   = (const float*)d_in[1];
    const float* kernals   = (const float*)d_in[2];
    const float* one_pad   = (const float*)d_in[3];
    const float* mlp_w     = (const float*)d_in[4];
    const float* mlp_b     = (const float*)d_in[5];
    const float* conv_w    = (const float*)d_in[6];
    const float* conv_b    = (const float*)d_in[7];
    const float* mlp_out_w = (const float*)d_in[8];
    const float* mlp_out_b = (const float*)d_in[9];
    const float* bn_gamma  = (const float*)d_in[10];
    const float* bn_beta   = (const float*)d_in[11];
    float* out = (float*)d_out;

    k_transpose<<<dim3(Nn/32, Cin/32, Bn), dim3(32,8)>>>(feature);
    k_prepw<<<(XSTRIDE*Cout)/256, 256>>>(conv_w, mlp_w, mlp_b,
                                         mlp_out_w, conv_b, mlp_out_b);
    k_knn<<<dim3(Nn/16, Bn), 64>>>(x);
    k_point<<<NP/2, 128>>>(x, kernals, one_pad);
    k_gemm<<<dim3(NP/128, 2), 256>>>();
    k_bnstat<<<Cout, 256>>>(bn_gamma, bn_beta);
    k_final<<<(Bn*Cout*Nn)/256, 256>>>(out);
}

// round 8
// speedup vs baseline: 1.3564x; 1.1147x over previous
#include <cuda_runtime.h>
#include <math.h>

// Problem constants
#define Bn   8
#define Nn   2048
#define Cin  64
#define Cout 64
#define Kn   20
#define KSn  20
#define NP   (Bn*Nn)      // 16384 points
#define XK   1504         // packed GEMM inner dim: 1280 agg + 160 g + 64 feat
#define XKH  752          // split-K half (47 tiles of 16)
#define XSTRIDE 1536      // padded row stride (float4 aligned)

// ---------------- scratch (__device__ globals, no allocation) ----------------
__device__ float g_Ft[NP*Cin];            // feature transposed [p][c]   (4 MB)
__device__ int   g_idx[NP*Kn];            // knn indices                 (1.3 MB)
__device__ float g_X[(size_t)NP*XSTRIDE]; // packed per-point vectors    (100 MB)
__device__ float g_Wt[XSTRIDE*Cout];      // packed weights [k][o]
__device__ float g_bias[Cout];
__device__ float g_o1a[Cout*NP];          // pre-BN output half A [o][p] (4 MB)
__device__ float g_o1b[Cout*NP];          // pre-BN output half B [o][p] (4 MB)
__device__ float g_scale[Cout];
__device__ float g_shift[Cout];

// packed f32x2 FMA: d = a*b + d  (two fp32 lanes per instruction)
#define FMA2(d, a, b) \
    asm("fma.rn.f32x2 %0, %1, %2, %0;" : "+l"(d) : "l"(a), "l"(b))

// ---------------- feature transpose: [B,C,N] -> [B*N, C] ----------------
__global__ void k_transpose(const float* __restrict__ f){
    __shared__ float tile[32][33];
    int b = blockIdx.z, c0 = blockIdx.y*32, n0 = blockIdx.x*32;
    int tx = threadIdx.x, ty = threadIdx.y;
    #pragma unroll
    for (int i=0;i<4;i++)
        tile[ty+8*i][tx] = f[b*Cin*Nn + (c0+ty+8*i)*Nn + n0+tx];
    __syncthreads();
    #pragma unroll
    for (int i=0;i<4;i++)
        g_Ft[(b*Nn + n0+ty+8*i)*Cin + c0+tx] = tile[tx][ty+8*i];
}

// ---------------- pack weights Wt[k][o] + bias ----------------
__global__ void k_prepw(const float* __restrict__ conv_w,
                        const float* __restrict__ mlp_w,
                        const float* __restrict__ mlp_b,
                        const float* __restrict__ mlp_out_w,
                        const float* __restrict__ conv_b,
                        const float* __restrict__ mlp_out_b){
    int id = blockIdx.x*blockDim.x + threadIdx.x;   // < 1536*64
    int k = id >> 6, o = id & 63;
    float v = 0.f;
    if (k < 1280){
        v = conv_w[o*2560 + k];
    } else if (k < 1440){
        int e = k - 1280;
        int m = e >> 3, j = e & 7;
        const float* cw = conv_w + o*2560 + 1280 + m;   // (64+c2)*20+m
        float s = 0.f;
        if (j < 7){
            for (int c2=0;c2<64;c2++) s += mlp_w[c2*7+j]*cw[c2*20];
        } else {
            for (int c2=0;c2<64;c2++) s += mlp_b[c2]*cw[c2*20];
        }
        v = s;
    } else if (k < XK){
        v = mlp_out_w[o*64 + (k-1440)];
    }
    g_Wt[k*64 + o] = v;
    if (id < 64) g_bias[id] = conv_b[id] + mlp_out_b[id];
}

// ---------------- KNN: warp per query, min-extraction top-20 ----------------
__global__ void k_knn(const float* __restrict__ x){
    __shared__ float spx[Nn];
    __shared__ float spy[Nn];
    __shared__ float spz[Nn];
    __shared__ float sdist[2][Nn];
    int t = threadIdx.x, w = t>>5, lane = t&31;
    int b = blockIdx.y;
    const float* xb = x + b*3*Nn;
    for (int e=t; e<Nn; e+=64){
        spx[e] = xb[e]; spy[e] = xb[Nn+e]; spz[e] = xb[2*Nn+e];
    }
    __syncthreads();
    float* sd = sdist[w];

    for (int i=0;i<8;i++){
        int q = blockIdx.x*16 + w*8 + i;
        float qx = spx[q], qy = spy[q], qz = spz[q];
        float mn = 3.0e38f; int amn = 0;
        #pragma unroll 8
        for (int tt=0; tt<64; tt++){
            int j = lane + (tt<<5);
            float dx = spx[j]-qx, dy = spy[j]-qy, dz = spz[j]-qz;
            float d2 = dx*dx + dy*dy + dz*dz;
            sd[j ^ (tt & 31)] = d2;
            if (d2 < mn){ mn = d2; amn = j; }
        }
        __syncwarp();
        int myn = 0;
        for (int kk=0; kk<Kn; kk++){
            float rv = mn; int ra = amn;
            #pragma unroll
            for (int off=16; off; off>>=1){
                float ov = __shfl_down_sync(0xffffffffu, rv, off);
                int   oa = __shfl_down_sync(0xffffffffu, ra, off);
                if (ov < rv){ rv = ov; ra = oa; }
            }
            int jst = __shfl_sync(0xffffffffu, ra, 0);
            if (lane == kk) myn = jst;
            int L = jst & 31;
            if (lane == L) sd[jst ^ ((jst>>5)&31)] = 3.0e38f;
            __syncwarp();
            int j1 = L + (lane<<5);
            int j2 = L + ((lane+32)<<5);
            float v1 = sd[j1 ^ lane];
            float v2 = sd[j2 ^ lane];
            float nv; int na;
            if (v1 <= v2){ nv = v1; na = j1; } else { nv = v2; na = j2; }
            #pragma unroll
            for (int off=16; off; off>>=1){
                float ov = __shfl_down_sync(0xffffffffu, nv, off);
                int   oa = __shfl_down_sync(0xffffffffu, na, off);
                if (ov < nv){ nv = ov; na = oa; }
            }
            nv = __shfl_sync(0xffffffffu, nv, 0);
            na = __shfl_sync(0xffffffffu, na, 0);
            if (lane == L){ mn = nv; amn = na; }
            __syncwarp();
        }
        if (lane < Kn) g_idx[(b*Nn + q)*Kn + lane] = myn;
    }
}

// ---------------- per-point: perm + agg + g-vector, direct STG ----------------
// 2 points per block, 64 threads per point; no sX staging — registers -> g_X.
__global__ void k_point(const float* __restrict__ x,
                        const float* __restrict__ kern,
                        const float* __restrict__ onepad){
    __shared__ int   sidx[2][Kn];
    __shared__ float sSelf[2][3];
    __shared__ float srel[2][Kn][3];
    __shared__ float sdst[2][Kn];
    __shared__ __align__(16) float sP[2][Kn][24];
    __shared__ float scol[2][KSn];
    __shared__ __align__(16) float sNF[2][Kn][Cin];

    int t = threadIdx.x;
    int half = t >> 6, u = t & 63;
    int p = blockIdx.x*2 + half;
    int b = p >> 11, n = p & 2047;
    float* xrow = g_X + (size_t)p*XSTRIDE;

    if (u < Kn) sidx[half][u] = g_idx[p*Kn + u];
    if (u < 3)  sSelf[half][u] = x[b*3*Nn + u*Nn + n];
    __syncthreads();

    if (u < Kn){
        int j = sidx[half][u];
        float rx = x[b*3*Nn +        j] - sSelf[half][0];
        float ry = x[b*3*Nn +   Nn + j] - sSelf[half][1];
        float rz = x[b*3*Nn + 2*Nn + j] - sSelf[half][2];
        srel[half][u][0] = rx; srel[half][u][1] = ry; srel[half][u][2] = rz;
        sdst[half][u] = sqrtf(rx*rx + ry*ry + rz*rz + 1e-12f);
    }
    // gather neighbor features: float4 lanes, 16 lanes per neighbor row
    #pragma unroll
    for (int e=u; e<Kn*16; e+=64){
        int k = e>>4, c4 = e&15;
        const float4* src = (const float4*)(g_Ft + (size_t)(b*Nn + sidx[half][k])*Cin);
        ((float4*)sNF[half][k])[c4] = src[c4];
    }
    // self feature row directly to g_X
    xrow[1440 + u] = g_Ft[p*Cin + u];
    __syncthreads();

    // raw perm = relu(rel @ kernals + one_padding)
    #pragma unroll
    for (int e=u; e<Kn*KSn; e+=64){
        int k = e/KSn, m = e - k*KSn;
        float s = srel[half][k][0]*kern[m] + srel[half][k][1]*kern[KSn+m]
                + srel[half][k][2]*kern[2*KSn+m] + onepad[e];
        sP[half][k][m] = fmaxf(s, 0.f);
    }
    __syncthreads();

    // double normalization over k + threshold, per column m
    if (u < KSn){
        float s1 = 0.f;
        #pragma unroll
        for (int k=0;k<Kn;k++) s1 += sP[half][k][u];
        float inv1 = 1.f/(s1 + 1e-6f);
        float v[Kn]; float s2 = 0.f;
        #pragma unroll
        for (int k=0;k<Kn;k++){ float q = sP[half][k][u]*inv1; q = q*q; v[k] = q; s2 += q; }
        float inv2 = 1.f/(s2 + 1e-6f);
        float s3 = 0.f;
        #pragma unroll
        for (int k=0;k<Kn;k++){
            float q = v[k]*inv2;
            q = (q > 0.1f) ? q : 0.f;
            sP[half][k][u] = q; s3 += q;
        }
        scol[half][u] = s3;
    }
    __syncthreads();

    // g[m][j]: x-path compressed to 8 components per m, direct STG
    #pragma unroll
    for (int e=u; e<160; e+=64){
        int m = e>>3, j = e&7;
        float val;
        if (j < 3) val = sSelf[half][j]*scol[half][m];
        else if (j == 7) val = scol[half][m];
        else if (j == 6){
            float s = 0.f;
            #pragma unroll
            for (int k=0;k<Kn;k++) s += sdst[half][k]*sP[half][k][m];
            val = s;
        } else {
            float s = 0.f;
            #pragma unroll
            for (int k=0;k<Kn;k++) s += srel[half][k][j-3]*sP[half][k][m];
            val = s;
        }
        xrow[1280 + m*8 + j] = val;
    }

    // agg[c][m] = sum_k NF[k][c]*P[k][m]; thread u owns channel c=u, all 20 m
    // registers -> g_X directly (u*20 floats = 80B, 16B-aligned)
    {
        float acc[20];
        #pragma unroll
        for (int i=0;i<20;i++) acc[i] = 0.f;
        #pragma unroll
        for (int k=0;k<Kn;k++){
            float vv = sNF[half][k][u];
            const float4* pr = (const float4*)sP[half][k];
            float4 q0 = pr[0], q1 = pr[1], q2 = pr[2], q3 = pr[3], q4 = pr[4];
            acc[0]+=vv*q0.x;  acc[1]+=vv*q0.y;  acc[2]+=vv*q0.z;  acc[3]+=vv*q0.w;
            acc[4]+=vv*q1.x;  acc[5]+=vv*q1.y;  acc[6]+=vv*q1.z;  acc[7]+=vv*q1.w;
            acc[8]+=vv*q2.x;  acc[9]+=vv*q2.y;  acc[10]+=vv*q2.z; acc[11]+=vv*q2.w;
            acc[12]+=vv*q3.x; acc[13]+=vv*q3.y; acc[14]+=vv*q3.z; acc[15]+=vv*q3.w;
            acc[16]+=vv*q4.x; acc[17]+=vv*q4.y; acc[18]+=vv*q4.z; acc[19]+=vv*q4.w;
        }
        float4* xr = (float4*)(xrow + u*KSn);
        xr[0] = make_float4(acc[0],acc[1],acc[2],acc[3]);
        xr[1] = make_float4(acc[4],acc[5],acc[6],acc[7]);
        xr[2] = make_float4(acc[8],acc[9],acc[10],acc[11]);
        xr[3] = make_float4(acc[12],acc[13],acc[14],acc[15]);
        xr[4] = make_float4(acc[16],acc[17],acc[18],acc[19]);
    }
}

// ---------------- GEMM (split-K=2, packed f32x2 FMA) ----------------
// thread tile: 8 consecutive p-rows (4 packed pairs) x 4 o-columns
__global__ void __launch_bounds__(256) k_gemm(){
    __shared__ float As[16][132];
    __shared__ __align__(16) float Bs[16][64];
    int t = threadIdx.x;
    int p0 = blockIdx.x * 128;
    int h  = blockIdx.y;
    int k0 = h * XKH;
    int tx = t & 15, ty = t >> 4;
    unsigned long long acc[4][4];    // [p-pair][o]
    #pragma unroll
    for (int i=0;i<4;i++)
        #pragma unroll
        for (int j=0;j<4;j++) acc[i][j] = 0ULL;

    for (int kt=k0; kt<k0+XKH; kt+=16){
        #pragma unroll
        for (int hh=0; hh<2; hh++){
            int e = t + hh*256;
            int row = e >> 2, seg = e & 3;
            float4 v = *(const float4*)(g_X + (size_t)(p0+row)*XSTRIDE + kt + seg*4);
            As[seg*4+0][row] = v.x; As[seg*4+1][row] = v.y;
            As[seg*4+2][row] = v.z; As[seg*4+3][row] = v.w;
        }
        {
            int kk = t >> 4, seg = t & 15;
            float4 wv = *(const float4*)(g_Wt + (kt+kk)*64 + seg*4);
            *(float4*)&Bs[kk][seg*4] = wv;
        }
        __syncthreads();
        #pragma unroll
        for (int k=0;k<16;k++){
            const float* ar = &As[k][ty*8];
            unsigned long long a0 = *(const unsigned long long*)(ar+0);
            unsigned long long a1 = *(const unsigned long long*)(ar+2);
            unsigned long long a2 = *(const unsigned long long*)(ar+4);
            unsigned long long a3 = *(const unsigned long long*)(ar+6);
            float4 bv = *(const float4*)&Bs[k][tx*4];
            unsigned long long b0,b1,b2,b3;
            asm("mov.b64 %0, {%1, %1};" : "=l"(b0) : "r"(__float_as_uint(bv.x)));
            asm("mov.b64 %0, {%1, %1};" : "=l"(b1) : "r"(__float_as_uint(bv.y)));
            asm("mov.b64 %0, {%1, %1};" : "=l"(b2) : "r"(__float_as_uint(bv.z)));
            asm("mov.b64 %0, {%1, %1};" : "=l"(b3) : "r"(__float_as_uint(bv.w)));
            FMA2(acc[0][0], a0, b0); FMA2(acc[0][1], a0, b1);
            FMA2(acc[0][2], a0, b2); FMA2(acc[0][3], a0, b3);
            FMA2(acc[1][0], a1, b0); FMA2(acc[1][1], a1, b1);
            FMA2(acc[1][2], a1, b2); FMA2(acc[1][3], a1, b3);
            FMA2(acc[2][0], a2, b0); FMA2(acc[2][1], a2, b1);
            FMA2(acc[2][2], a2, b2); FMA2(acc[2][3], a2, b3);
            FMA2(acc[3][0], a3, b0); FMA2(acc[3][1], a3, b1);
            FMA2(acc[3][2], a3, b2); FMA2(acc[3][3], a3, b3);
        }
        __syncthreads();
    }
    float* dst = h ? g_o1b : g_o1a;
    #pragma unroll
    for (int j=0;j<4;j++){
        int o = tx*4 + j;
        float bb = h ? 0.f : g_bias[o];
        #pragma unroll
        for (int i=0;i<4;i++){
            float lo = __uint_as_float((unsigned)(acc[i][j] & 0xffffffffULL));
            float hi = __uint_as_float((unsigned)(acc[i][j] >> 32));
            *(float2*)&dst[o*NP + p0 + ty*8 + i*2] = make_float2(lo+bb, hi+bb);
        }
    }
}

// ---------------- BN statistics per channel ----------------
__global__ void k_bnstat(const float* __restrict__ gamma,
                         const float* __restrict__ beta){
    int o = blockIdx.x, t = threadIdx.x;
    const float* ra = g_o1a + o*NP;
    const float* rb = g_o1b + o*NP;
    double s = 0.0, s2 = 0.0;
    for (int i=t; i<NP; i+=256){
        double v = (double)(ra[i] + rb[i]);
        s += v; s2 += v*v;
    }
    __shared__ double sh1[256], sh2[256];
    sh1[t] = s; sh2[t] = s2;
    __syncthreads();
    for (int off=128; off; off>>=1){
        if (t < off){ sh1[t] += sh1[t+off]; sh2[t] += sh2[t+off]; }
        __syncthreads();
    }
    if (t == 0){
        double mean = sh1[0] / (double)NP;
        double var  = sh2[0] / (double)NP - mean*mean;
        float sc = gamma[o] / sqrtf((float)var + 1e-5f);
        g_scale[o] = sc;
        g_shift[o] = beta[o] - (float)mean * sc;
    }
}

// ---------------- finalize: affine BN + layout [B,C,N] ----------------
__global__ void k_final(float* __restrict__ out){
    int e = blockIdx.x*blockDim.x + threadIdx.x;   // < 1048576
    int n = e & 2047;
    int o = (e >> 11) & 63;
    int b = e >> 17;
    int idx = o*NP + b*Nn + n;
    out[e] = (g_o1a[idx] + g_o1b[idx]) * g_scale[o] + g_shift[o];
}

// ---------------- launch ----------------
extern "C" void kernel_launch(void* const* d_in, const int* in_sizes, int n_in,
                              void* d_out, int out_size){
    (void)in_sizes; (void)n_in; (void)out_size;
    const float* x         = (const float*)d_in[0];
    const float* feature   = (const float*)d_in[1];
    const float* kernals   = (const float*)d_in[2];
    const float* one_pad   = (const float*)d_in[3];
    const float* mlp_w     = (const float*)d_in[4];
    const float* mlp_b     = (const float*)d_in[5];
    const float* conv_w    = (const float*)d_in[6];
    const float* conv_b    = (const float*)d_in[7];
    const float* mlp_out_w = (const float*)d_in[8];
    const float* mlp_out_b = (const float*)d_in[9];
    const float* bn_gamma  = (const float*)d_in[10];
    const float* bn_beta   = (const float*)d_in[11];
    float* out = (float*)d_out;

    k_transpose<<<dim3(Nn/32, Cin/32, Bn), dim3(32,8)>>>(feature);
    k_prepw<<<(XSTRIDE*Cout)/256, 256>>>(conv_w, mlp_w, mlp_b,
                                         mlp_out_w, conv_b, mlp_out_b);
    k_knn<<<dim3(Nn/16, Bn), 64>>>(x);
    k_point<<<NP/2, 128>>>(x, kernals, one_pad);
    k_gemm<<<dim3(NP/128, 2), 256>>>();
    k_bnstat<<<Cout, 256>>>(bn_gamma, bn_beta);
    k_final<<<(Bn*Cout*Nn)/256, 256>>>(out);
}

// round 9
// speedup vs baseline: 1.5712x; 1.1583x over previous
#include <cuda_runtime.h>
#include <math.h>

// Problem constants
#define Bn   8
#define Nn   2048
#define Cin  64
#define Cout 64
#define Kn   20
#define KSn  20
#define NP   (Bn*Nn)      // 16384 points
#define XK   1504         // packed GEMM inner dim: 1280 agg + 160 g + 64 feat
#define XKH  752          // split-K half (47 tiles of 16)
#define XSTRIDE 1536      // padded row stride (float4 aligned)

// ---------------- scratch (__device__ globals, no allocation) ----------------
__device__ float g_Ft[NP*Cin];            // feature transposed [p][c]   (4 MB)
__device__ int   g_idx[NP*Kn];            // knn indices                 (1.3 MB)
__device__ float g_X[(size_t)NP*XSTRIDE]; // packed per-point vectors    (100 MB)
__device__ float g_Wt[XSTRIDE*Cout];      // packed weights [k][o]
__device__ float g_bias[Cout];
__device__ float g_o1a[Cout*NP];          // pre-BN output half A [o][p] (4 MB)
__device__ float g_o1b[Cout*NP];          // pre-BN output half B [o][p] (4 MB)
__device__ float g_scale[Cout];
__device__ float g_shift[Cout];

// packed f32x2 FMA: d = a*b + d  (two fp32 lanes per instruction)
#define FMA2(d, a, b) \
    asm("fma.rn.f32x2 %0, %1, %2, %0;" : "+l"(d) : "l"(a), "l"(b))

// ---------------- feature transpose: [B,C,N] -> [B*N, C] ----------------
__global__ void k_transpose(const float* __restrict__ f){
    __shared__ float tile[32][33];
    int b = blockIdx.z, c0 = blockIdx.y*32, n0 = blockIdx.x*32;
    int tx = threadIdx.x, ty = threadIdx.y;
    #pragma unroll
    for (int i=0;i<4;i++)
        tile[ty+8*i][tx] = f[b*Cin*Nn + (c0+ty+8*i)*Nn + n0+tx];
    __syncthreads();
    #pragma unroll
    for (int i=0;i<4;i++)
        g_Ft[(b*Nn + n0+ty+8*i)*Cin + c0+tx] = tile[tx][ty+8*i];
}

// ---------------- pack weights Wt[k][o] + bias ----------------
// agg block is m-major: X position q (q<1280) holds agg[c][m], c=q&63, m=q>>6
__global__ void k_prepw(const float* __restrict__ conv_w,
                        const float* __restrict__ mlp_w,
                        const float* __restrict__ mlp_b,
                        const float* __restrict__ mlp_out_w,
                        const float* __restrict__ conv_b,
                        const float* __restrict__ mlp_out_b){
    int id = blockIdx.x*blockDim.x + threadIdx.x;   // < 1536*64
    int k = id >> 6, o = id & 63;
    float v = 0.f;
    if (k < 1280){
        int c = k & 63, m = k >> 6;
        v = conv_w[o*2560 + c*KSn + m];
    } else if (k < 1440){
        int e = k - 1280;
        int m = e >> 3, j = e & 7;
        const float* cw = conv_w + o*2560 + 1280 + m;   // (64+c2)*20+m
        float s = 0.f;
        if (j < 7){
            for (int c2=0;c2<64;c2++) s += mlp_w[c2*7+j]*cw[c2*20];
        } else {
            for (int c2=0;c2<64;c2++) s += mlp_b[c2]*cw[c2*20];
        }
        v = s;
    } else if (k < XK){
        v = mlp_out_w[o*64 + (k-1440)];
    }
    g_Wt[k*64 + o] = v;
    if (id < 64) g_bias[id] = conv_b[id] + mlp_out_b[id];
}

// ---------------- KNN: warp per query, min-extraction top-20 ----------------
// argmin via redux.sync.min.u32 (positive fp32 bits are order-isomorphic)
__global__ void k_knn(const float* __restrict__ x){
    __shared__ float spx[Nn];
    __shared__ float spy[Nn];
    __shared__ float spz[Nn];
    __shared__ float sdist[2][Nn];
    int t = threadIdx.x, w = t>>5, lane = t&31;
    int b = blockIdx.y;
    const float* xb = x + b*3*Nn;
    for (int e=t; e<Nn; e+=64){
        spx[e] = xb[e]; spy[e] = xb[Nn+e]; spz[e] = xb[2*Nn+e];
    }
    __syncthreads();
    float* sd = sdist[w];

    for (int i=0;i<8;i++){
        int q = blockIdx.x*16 + w*8 + i;
        float qx = spx[q], qy = spy[q], qz = spz[q];
        float mn = 3.0e38f; int amn = 0;
        #pragma unroll 8
        for (int tt=0; tt<64; tt++){
            int j = lane + (tt<<5);
            float dx = spx[j]-qx, dy = spy[j]-qy, dz = spz[j]-qz;
            float d2 = dx*dx + dy*dy + dz*dz;
            sd[j ^ (tt & 31)] = d2;
            if (d2 < mn){ mn = d2; amn = j; }
        }
        __syncwarp();
        int myn = 0;
        for (int kk=0; kk<Kn; kk++){
            // global argmin over lane caches (redux + ballot + shfl)
            unsigned rb_ = __reduce_min_sync(0xffffffffu, __float_as_uint(mn));
            unsigned bmsk = __ballot_sync(0xffffffffu, __float_as_uint(mn)==rb_);
            int src = __ffs(bmsk) - 1;
            int jst = __shfl_sync(0xffffffffu, amn, src);
            if (lane == kk) myn = jst;
            int L = jst & 31;
            if (lane == L) sd[jst ^ ((jst>>5)&31)] = 3.0e38f;
            __syncwarp();
            // 32 lanes rescan owner L's 64 slots (2 each), conflict-free banks
            int j1 = L + (lane<<5);
            int j2 = L + ((lane+32)<<5);
            float v1 = sd[j1 ^ lane];
            float v2 = sd[j2 ^ lane];
            float nv; int na;
            if (v1 <= v2){ nv = v1; na = j1; } else { nv = v2; na = j2; }
            unsigned rb2 = __reduce_min_sync(0xffffffffu, __float_as_uint(nv));
            unsigned bm2 = __ballot_sync(0xffffffffu, __float_as_uint(nv)==rb2);
            int src2 = __ffs(bm2) - 1;
            int na2 = __shfl_sync(0xffffffffu, na, src2);
            if (lane == L){ mn = __uint_as_float(rb2); amn = na2; }
            __syncwarp();
        }
        if (lane < Kn) g_idx[(b*Nn + q)*Kn + lane] = myn;
    }
}

// ---------------- per-point: perm + agg + g-vector ----------------
// 2 points per block, 64 threads per point; agg reads g_Ft directly
// (coalesced LDG) and stores m-major (coalesced STG.32).
__global__ void k_point(const float* __restrict__ x,
                        const float* __restrict__ kern,
                        const float* __restrict__ onepad){
    __shared__ int   sidx[2][Kn];
    __shared__ float sSelf[2][3];
    __shared__ float srel[2][Kn][3];
    __shared__ float sdst[2][Kn];
    __shared__ __align__(16) float sP[2][Kn][24];
    __shared__ float scol[2][KSn];

    int t = threadIdx.x;
    int half = t >> 6, u = t & 63;
    int p = blockIdx.x*2 + half;
    int b = p >> 11, n = p & 2047;
    float* xrow = g_X + (size_t)p*XSTRIDE;

    if (u < Kn) sidx[half][u] = g_idx[p*Kn + u];
    if (u < 3)  sSelf[half][u] = x[b*3*Nn + u*Nn + n];
    __syncthreads();

    if (u < Kn){
        int j = sidx[half][u];
        float rx = x[b*3*Nn +        j] - sSelf[half][0];
        float ry = x[b*3*Nn +   Nn + j] - sSelf[half][1];
        float rz = x[b*3*Nn + 2*Nn + j] - sSelf[half][2];
        srel[half][u][0] = rx; srel[half][u][1] = ry; srel[half][u][2] = rz;
        sdst[half][u] = sqrtf(rx*rx + ry*ry + rz*rz + 1e-12f);
    }
    // self feature row directly to g_X
    xrow[1440 + u] = g_Ft[p*Cin + u];
    __syncthreads();

    // raw perm = relu(rel @ kernals + one_padding)
    #pragma unroll
    for (int e=u; e<Kn*KSn; e+=64){
        int k = e/KSn, m = e - k*KSn;
        float s = srel[half][k][0]*kern[m] + srel[half][k][1]*kern[KSn+m]
                + srel[half][k][2]*kern[2*KSn+m] + onepad[e];
        sP[half][k][m] = fmaxf(s, 0.f);
    }
    __syncthreads();

    // double normalization over k + threshold, per column m
    if (u < KSn){
        float s1 = 0.f;
        #pragma unroll
        for (int k=0;k<Kn;k++) s1 += sP[half][k][u];
        float inv1 = 1.f/(s1 + 1e-6f);
        float v[Kn]; float s2 = 0.f;
        #pragma unroll
        for (int k=0;k<Kn;k++){ float q = sP[half][k][u]*inv1; q = q*q; v[k] = q; s2 += q; }
        float inv2 = 1.f/(s2 + 1e-6f);
        float s3 = 0.f;
        #pragma unroll
        for (int k=0;k<Kn;k++){
            float q = v[k]*inv2;
            q = (q > 0.1f) ? q : 0.f;
            sP[half][k][u] = q; s3 += q;
        }
        scol[half][u] = s3;
    }
    __syncthreads();

    // g[m][j]: x-path compressed to 8 components per m, direct STG
    #pragma unroll
    for (int e=u; e<160; e+=64){
        int m = e>>3, j = e&7;
        float val;
        if (j < 3) val = sSelf[half][j]*scol[half][m];
        else if (j == 7) val = scol[half][m];
        else if (j == 6){
            float s = 0.f;
            #pragma unroll
            for (int k=0;k<Kn;k++) s += sdst[half][k]*sP[half][k][m];
            val = s;
        } else {
            float s = 0.f;
            #pragma unroll
            for (int k=0;k<Kn;k++) s += srel[half][k][j-3]*sP[half][k][m];
            val = s;
        }
        xrow[1280 + m*8 + j] = val;
    }

    // agg[c][m] = sum_k NF[k][c]*P[k][m]; thread u = channel c, all 20 m.
    // NF read straight from g_Ft (coalesced), result stored m-major (coalesced).
    {
        const int base = b*Nn;
        float acc[20];
        #pragma unroll
        for (int i=0;i<20;i++) acc[i] = 0.f;
        #pragma unroll
        for (int k=0;k<Kn;k++){
            float vv = g_Ft[(size_t)(base + sidx[half][k])*Cin + u];
            const float4* pr = (const float4*)sP[half][k];
            float4 q0 = pr[0], q1 = pr[1], q2 = pr[2], q3 = pr[3], q4 = pr[4];
            acc[0]+=vv*q0.x;  acc[1]+=vv*q0.y;  acc[2]+=vv*q0.z;  acc[3]+=vv*q0.w;
            acc[4]+=vv*q1.x;  acc[5]+=vv*q1.y;  acc[6]+=vv*q1.z;  acc[7]+=vv*q1.w;
            acc[8]+=vv*q2.x;  acc[9]+=vv*q2.y;  acc[10]+=vv*q2.z; acc[11]+=vv*q2.w;
            acc[12]+=vv*q3.x; acc[13]+=vv*q3.y; acc[14]+=vv*q3.z; acc[15]+=vv*q3.w;
            acc[16]+=vv*q4.x; acc[17]+=vv*q4.y; acc[18]+=vv*q4.z; acc[19]+=vv*q4.w;
        }
        #pragma unroll
        for (int m=0;m<20;m++)
            xrow[m*64 + u] = acc[m];
    }
}

// ---------------- GEMM (split-K=2, packed f32x2 FMA) ----------------
// thread tile: 8 consecutive p-rows (4 packed pairs) x 4 o-columns
__global__ void __launch_bounds__(256) k_gemm(){
    __shared__ float As[16][132];
    __shared__ __align__(16) float Bs[16][64];
    int t = threadIdx.x;
    int p0 = blockIdx.x * 128;
    int h  = blockIdx.y;
    int k0 = h * XKH;
    int tx = t & 15, ty = t >> 4;
    unsigned long long acc[4][4];    // [p-pair][o]
    #pragma unroll
    for (int i=0;i<4;i++)
        #pragma unroll
        for (int j=0;j<4;j++) acc[i][j] = 0ULL;

    for (int kt=k0; kt<k0+XKH; kt+=16){
        #pragma unroll
        for (int hh=0; hh<2; hh++){
            int e = t + hh*256;
            int row = e >> 2, seg = e & 3;
            float4 v = *(const float4*)(g_X + (size_t)(p0+row)*XSTRIDE + kt + seg*4);
            As[seg*4+0][row] = v.x; As[seg*4+1][row] = v.y;
            As[seg*4+2][row] = v.z; As[seg*4+3][row] = v.w;
        }
        {
            int kk = t >> 4, seg = t & 15;
            float4 wv = *(const float4*)(g_Wt + (kt+kk)*64 + seg*4);
            *(float4*)&Bs[kk][seg*4] = wv;
        }
        __syncthreads();
        #pragma unroll
        for (int k=0;k<16;k++){
            const float* ar = &As[k][ty*8];
            unsigned long long a0 = *(const unsigned long long*)(ar+0);
            unsigned long long a1 = *(const unsigned long long*)(ar+2);
            unsigned long long a2 = *(const unsigned long long*)(ar+4);
            unsigned long long a3 = *(const unsigned long long*)(ar+6);
            float4 bv = *(const float4*)&Bs[k][tx*4];
            unsigned long long b0,b1,b2,b3;
            asm("mov.b64 %0, {%1, %1};" : "=l"(b0) : "r"(__float_as_uint(bv.x)));
            asm("mov.b64 %0, {%1, %1};" : "=l"(b1) : "r"(__float_as_uint(bv.y)));
            asm("mov.b64 %0, {%1, %1};" : "=l"(b2) : "r"(__float_as_uint(bv.z)));
            asm("mov.b64 %0, {%1, %1};" : "=l"(b3) : "r"(__float_as_uint(bv.w)));
            FMA2(acc[0][0], a0, b0); FMA2(acc[0][1], a0, b1);
            FMA2(acc[0][2], a0, b2); FMA2(acc[0][3], a0, b3);
            FMA2(acc[1][0], a1, b0); FMA2(acc[1][1], a1, b1);
            FMA2(acc[1][2], a1, b2); FMA2(acc[1][3], a1, b3);
            FMA2(acc[2][0], a2, b0); FMA2(acc[2][1], a2, b1);
            FMA2(acc[2][2], a2, b2); FMA2(acc[2][3], a2, b3);
            FMA2(acc[3][0], a3, b0); FMA2(acc[3][1], a3, b1);
            FMA2(acc[3][2], a3, b2); FMA2(acc[3][3], a3, b3);
        }
        __syncthreads();
    }
    float* dst = h ? g_o1b : g_o1a;
    #pragma unroll
    for (int j=0;j<4;j++){
        int o = tx*4 + j;
        float bb = h ? 0.f : g_bias[o];
        #pragma unroll
        for (int i=0;i<4;i++){
            float lo = __uint_as_float((unsigned)(acc[i][j] & 0xffffffffULL));
            float hi = __uint_as_float((unsigned)(acc[i][j] >> 32));
            *(float2*)&dst[o*NP + p0 + ty*8 + i*2] = make_float2(lo+bb, hi+bb);
        }
    }
}

// ---------------- BN statistics per channel ----------------
__global__ void k_bnstat(const float* __restrict__ gamma,
                         const float* __restrict__ beta){
    int o = blockIdx.x, t = threadIdx.x;
    const float* ra = g_o1a + o*NP;
    const float* rb = g_o1b + o*NP;
    double s = 0.0, s2 = 0.0;
    for (int i=t; i<NP; i+=256){
        double v = (double)(ra[i] + rb[i]);
        s += v; s2 += v*v;
    }
    __shared__ double sh1[256], sh2[256];
    sh1[t] = s; sh2[t] = s2;
    __syncthreads();
    for (int off=128; off; off>>=1){
        if (t < off){ sh1[t] += sh1[t+off]; sh2[t] += sh2[t+off]; }
        __syncthreads();
    }
    if (t == 0){
        double mean = sh1[0] / (double)NP;
        double var  = sh2[0] / (double)NP - mean*mean;
        float sc = gamma[o] / sqrtf((float)var + 1e-5f);
        g_scale[o] = sc;
        g_shift[o] = beta[o] - (float)mean * sc;
    }
}

// ---------------- finalize: affine BN + layout [B,C,N] ----------------
__global__ void k_final(float* __restrict__ out){
    int e = blockIdx.x*blockDim.x + threadIdx.x;   // < 1048576
    int n = e & 2047;
    int o = (e >> 11) & 63;
    int b = e >> 17;
    int idx = o*NP + b*Nn + n;
    out[e] = (g_o1a[idx] + g_o1b[idx]) * g_scale[o] + g_shift[o];
}

// ---------------- launch ----------------
extern "C" void kernel_launch(void* const* d_in, const int* in_sizes, int n_in,
                              void* d_out, int out_size){
    (void)in_sizes; (void)n_in; (void)out_size;
    const float* x         = (const float*)d_in[0];
    const float* feature   = (const float*)d_in[1];
    const float* kernals   = (const float*)d_in[2];
    const float* one_pad   = (const float*)d_in[3];
    const float* mlp_w     = (const float*)d_in[4];
    const float* mlp_b     = (const float*)d_in[5];
    const float* conv_w    = (const float*)d_in[6];
    const float* conv_b    = (const float*)d_in[7];
    const float* mlp_out_w = (const float*)d_in[8];
    const float* mlp_out_b = (const float*)d_in[9];
    const float* bn_gamma  = (const float*)d_in[10];
    const float* bn_beta   = (const float*)d_in[11];
    float* out = (float*)d_out;

    k_transpose<<<dim3(Nn/32, Cin/32, Bn), dim3(32,8)>>>(feature);
    k_prepw<<<(XSTRIDE*Cout)/256, 256>>>(conv_w, mlp_w, mlp_b,
                                         mlp_out_w, conv_b, mlp_out_b);
    k_knn<<<dim3(Nn/16, Bn), 64>>>(x);
    k_point<<<NP/2, 128>>>(x, kernals, one_pad);
    k_gemm<<<dim3(NP/128, 2), 256>>>();
    k_bnstat<<<Cout, 256>>>(bn_gamma, bn_beta);
    k_final<<<(Bn*Cout*Nn)/256, 256>>>(out);
}

// round 12
// speedup vs baseline: 1.6436x; 1.0461x over previous
#include <cuda_runtime.h>
#include <math.h>

// Problem constants
#define Bn   8
#define Nn   2048
#define Cin  64
#define Cout 64
#define Kn   20
#define KSn  20
#define NP   (Bn*Nn)      // 16384 points
#define XK   1504         // packed GEMM inner dim: 1280 agg + 160 g + 64 feat
#define XKH  752          // split-K half (47 tiles of 16)
#define XSTRIDE 1536      // padded row stride (float4 aligned)

// ---------------- scratch (__device__ globals, no allocation) ----------------
__device__ float g_Ft[NP*Cin];            // feature transposed [p][c]   (4 MB)
__device__ int   g_idx[NP*Kn];            // knn indices                 (1.3 MB)
__device__ float g_X[(size_t)NP*XSTRIDE]; // packed per-point vectors    (100 MB)
__device__ float g_Wt[XSTRIDE*Cout];      // packed weights [k][o]
__device__ float g_bias[Cout];
__device__ float g_o1a[Cout*NP];          // pre-BN output half A [o][p] (4 MB)
__device__ float g_o1b[Cout*NP];          // pre-BN output half B [o][p] (4 MB)
__device__ float g_scale[Cout];
__device__ float g_shift[Cout];

// packed f32x2 FMA: d = a*b + d  (two fp32 lanes per instruction)
#define FMA2(d, a, b) \
    asm("fma.rn.f32x2 %0, %1, %2, %0;" : "+l"(d) : "l"(a), "l"(b))

// ---------------- feature transpose: [B,C,N] -> [B*N, C] ----------------
__global__ void k_transpose(const float* __restrict__ f){
    __shared__ float tile[32][33];
    int b = blockIdx.z, c0 = blockIdx.y*32, n0 = blockIdx.x*32;
    int tx = threadIdx.x, ty = threadIdx.y;
    #pragma unroll
    for (int i=0;i<4;i++)
        tile[ty+8*i][tx] = f[b*Cin*Nn + (c0+ty+8*i)*Nn + n0+tx];
    __syncthreads();
    #pragma unroll
    for (int i=0;i<4;i++)
        g_Ft[(b*Nn + n0+ty+8*i)*Cin + c0+tx] = tile[tx][ty+8*i];
}

// ---------------- pack weights Wt[k][o] + bias ----------------
// agg block is m-major: X position q (q<1280) holds agg[c][m], c=q&63, m=q>>6
__global__ void k_prepw(const float* __restrict__ conv_w,
                        const float* __restrict__ mlp_w,
                        const float* __restrict__ mlp_b,
                        const float* __restrict__ mlp_out_w,
                        const float* __restrict__ conv_b,
                        const float* __restrict__ mlp_out_b){
    int id = blockIdx.x*blockDim.x + threadIdx.x;   // < 1536*64
    int k = id >> 6, o = id & 63;
    float v = 0.f;
    if (k < 1280){
        int c = k & 63, m = k >> 6;
        v = conv_w[o*2560 + c*KSn + m];
    } else if (k < 1440){
        int e = k - 1280;
        int m = e >> 3, j = e & 7;
        const float* cw = conv_w + o*2560 + 1280 + m;   // (64+c2)*20+m
        float s = 0.f;
        if (j < 7){
            for (int c2=0;c2<64;c2++) s += mlp_w[c2*7+j]*cw[c2*20];
        } else {
            for (int c2=0;c2<64;c2++) s += mlp_b[c2]*cw[c2*20];
        }
        v = s;
    } else if (k < XK){
        v = mlp_out_w[o*64 + (k-1440)];
    }
    g_Wt[k*64 + o] = v;
    if (id < 64) g_bias[id] = conv_b[id] + mlp_out_b[id];
}

// ---------------- KNN: warp per query, min-extraction top-20 ----------------
// argmin via redux.sync.min.u32 (positive fp32 bits are order-isomorphic)
__global__ void k_knn(const float* __restrict__ x){
    __shared__ float spx[Nn];
    __shared__ float spy[Nn];
    __shared__ float spz[Nn];
    __shared__ float sdist[2][Nn];
    int t = threadIdx.x, w = t>>5, lane = t&31;
    int b = blockIdx.y;
    const float* xb = x + b*3*Nn;
    for (int e=t; e<Nn; e+=64){
        spx[e] = xb[e]; spy[e] = xb[Nn+e]; spz[e] = xb[2*Nn+e];
    }
    __syncthreads();
    float* sd = sdist[w];

    for (int i=0;i<8;i++){
        int q = blockIdx.x*16 + w*8 + i;
        float qx = spx[q], qy = spy[q], qz = spz[q];
        float mn = 3.0e38f; int amn = 0;
        #pragma unroll 8
        for (int tt=0; tt<64; tt++){
            int j = lane + (tt<<5);
            float dx = spx[j]-qx, dy = spy[j]-qy, dz = spz[j]-qz;
            float d2 = dx*dx + dy*dy + dz*dz;
            sd[j ^ (tt & 31)] = d2;
            if (d2 < mn){ mn = d2; amn = j; }
        }
        __syncwarp();
        int myn = 0;
        for (int kk=0; kk<Kn; kk++){
            unsigned rb_ = __reduce_min_sync(0xffffffffu, __float_as_uint(mn));
            unsigned bmsk = __ballot_sync(0xffffffffu, __float_as_uint(mn)==rb_);
            int src = __ffs(bmsk) - 1;
            int jst = __shfl_sync(0xffffffffu, amn, src);
            if (lane == kk) myn = jst;
            int L = jst & 31;
            if (lane == L) sd[jst ^ ((jst>>5)&31)] = 3.0e38f;
            __syncwarp();
            int j1 = L + (lane<<5);
            int j2 = L + ((lane+32)<<5);
            float v1 = sd[j1 ^ lane];
            float v2 = sd[j2 ^ lane];
            float nv; int na;
            if (v1 <= v2){ nv = v1; na = j1; } else { nv = v2; na = j2; }
            unsigned rb2 = __reduce_min_sync(0xffffffffu, __float_as_uint(nv));
            unsigned bm2 = __ballot_sync(0xffffffffu, __float_as_uint(nv)==rb2);
            int src2 = __ffs(bm2) - 1;
            int na2 = __shfl_sync(0xffffffffu, na, src2);
            if (lane == L){ mn = __uint_as_float(rb2); amn = na2; }
            __syncwarp();
        }
        if (lane < Kn) g_idx[(b*Nn + q)*Kn + lane] = myn;
    }
}

// ---------------- per-point: perm + agg + g-vector ----------------
__global__ void k_point(const float* __restrict__ x,
                        const float* __restrict__ kern,
                        const float* __restrict__ onepad){
    __shared__ int   sidx[2][Kn];
    __shared__ float sSelf[2][3];
    __shared__ float srel[2][Kn][3];
    __shared__ float sdst[2][Kn];
    __shared__ __align__(16) float sP[2][Kn][24];
    __shared__ float scol[2][KSn];

    int t = threadIdx.x;
    int half = t >> 6, u = t & 63;
    int p = blockIdx.x*2 + half;
    int b = p >> 11, n = p & 2047;
    float* xrow = g_X + (size_t)p*XSTRIDE;

    if (u < Kn) sidx[half][u] = g_idx[p*Kn + u];
    if (u < 3)  sSelf[half][u] = x[b*3*Nn + u*Nn + n];
    __syncthreads();

    if (u < Kn){
        int j = sidx[half][u];
        float rx = x[b*3*Nn +        j] - sSelf[half][0];
        float ry = x[b*3*Nn +   Nn + j] - sSelf[half][1];
        float rz = x[b*3*Nn + 2*Nn + j] - sSelf[half][2];
        srel[half][u][0] = rx; srel[half][u][1] = ry; srel[half][u][2] = rz;
        sdst[half][u] = sqrtf(rx*rx + ry*ry + rz*rz + 1e-12f);
    }
    // self feature row directly to g_X
    xrow[1440 + u] = g_Ft[p*Cin + u];
    __syncthreads();

    // raw perm = relu(rel @ kernals + one_padding)
    #pragma unroll
    for (int e=u; e<Kn*KSn; e+=64){
        int k = e/KSn, m = e - k*KSn;
        float s = srel[half][k][0]*kern[m] + srel[half][k][1]*kern[KSn+m]
                + srel[half][k][2]*kern[2*KSn+m] + onepad[e];
        sP[half][k][m] = fmaxf(s, 0.f);
    }
    __syncthreads();

    // double normalization over k + threshold, per column m
    if (u < KSn){
        float s1 = 0.f;
        #pragma unroll
        for (int k=0;k<Kn;k++) s1 += sP[half][k][u];
        float inv1 = 1.f/(s1 + 1e-6f);
        float v[Kn]; float s2 = 0.f;
        #pragma unroll
        for (int k=0;k<Kn;k++){ float q = sP[half][k][u]*inv1; q = q*q; v[k] = q; s2 += q; }
        float inv2 = 1.f/(s2 + 1e-6f);
        float s3 = 0.f;
        #pragma unroll
        for (int k=0;k<Kn;k++){
            float q = v[k]*inv2;
            q = (q > 0.1f) ? q : 0.f;
            sP[half][k][u] = q; s3 += q;
        }
        scol[half][u] = s3;
    }
    __syncthreads();

    // g[m][j]: x-path compressed to 8 components per m, direct STG
    #pragma unroll
    for (int e=u; e<160; e+=64){
        int m = e>>3, j = e&7;
        float val;
        if (j < 3) val = sSelf[half][j]*scol[half][m];
        else if (j == 7) val = scol[half][m];
        else if (j == 6){
            float s = 0.f;
            #pragma unroll
            for (int k=0;k<Kn;k++) s += sdst[half][k]*sP[half][k][m];
            val = s;
        } else {
            float s = 0.f;
            #pragma unroll
            for (int k=0;k<Kn;k++) s += srel[half][k][j-3]*sP[half][k][m];
            val = s;
        }
        xrow[1280 + m*8 + j] = val;
    }

    // agg[c][m] = sum_k NF[k][c]*P[k][m]; thread u = channel c, all 20 m.
    {
        const int base = b*Nn;
        float acc[20];
        #pragma unroll
        for (int i=0;i<20;i++) acc[i] = 0.f;
        #pragma unroll
        for (int k=0;k<Kn;k++){
            float vv = g_Ft[(size_t)(base + sidx[half][k])*Cin + u];
            const float4* pr = (const float4*)sP[half][k];
            float4 q0 = pr[0], q1 = pr[1], q2 = pr[2], q3 = pr[3], q4 = pr[4];
            acc[0]+=vv*q0.x;  acc[1]+=vv*q0.y;  acc[2]+=vv*q0.z;  acc[3]+=vv*q0.w;
            acc[4]+=vv*q1.x;  acc[5]+=vv*q1.y;  acc[6]+=vv*q1.z;  acc[7]+=vv*q1.w;
            acc[8]+=vv*q2.x;  acc[9]+=vv*q2.y;  acc[10]+=vv*q2.z; acc[11]+=vv*q2.w;
            acc[12]+=vv*q3.x; acc[13]+=vv*q3.y; acc[14]+=vv*q3.z; acc[15]+=vv*q3.w;
            acc[16]+=vv*q4.x; acc[17]+=vv*q4.y; acc[18]+=vv*q4.z; acc[19]+=vv*q4.w;
        }
        #pragma unroll
        for (int m=0;m<20;m++)
            xrow[m*64 + u] = acc[m];
    }
}

// ---------------- GEMM (split-K=2, FFMA2, double-buffered smem) ----------------
// thread tile: 8 consecutive p-rows (4 packed pairs) x 4 o-columns
__global__ void __launch_bounds__(256) k_gemm(){
    __shared__ float As[2][16][132];
    __shared__ __align__(16) float Bs[2][16][64];
    int t = threadIdx.x;
    int p0 = blockIdx.x * 128;
    int h  = blockIdx.y;
    int k0 = h * XKH;
    int tx = t & 15, ty = t >> 4;
    int arow = t >> 2, aseg = t & 3;       // As loader mapping (rows 0..63 / +64)
    int bk   = t >> 4, bseg = t & 15;      // Bs loader mapping
    unsigned long long acc[4][4];
    #pragma unroll
    for (int i=0;i<4;i++)
        #pragma unroll
        for (int j=0;j<4;j++) acc[i][j] = 0ULL;

    const float* a0p = g_X + (size_t)(p0+arow)*XSTRIDE + aseg*4;
    const float* a1p = g_X + (size_t)(p0+64+arow)*XSTRIDE + aseg*4;
    const float* bp  = g_Wt + bk*64 + bseg*4;

    // preload tile 0 into buffer 0
    {
        float4 v0 = *(const float4*)(a0p + k0);
        float4 v1 = *(const float4*)(a1p + k0);
        float4 wv = *(const float4*)(bp + k0*64);
        As[0][aseg*4+0][arow] = v0.x; As[0][aseg*4+1][arow] = v0.y;
        As[0][aseg*4+2][arow] = v0.z; As[0][aseg*4+3][arow] = v0.w;
        As[0][aseg*4+0][64+arow] = v1.x; As[0][aseg*4+1][64+arow] = v1.y;
        As[0][aseg*4+2][64+arow] = v1.z; As[0][aseg*4+3][64+arow] = v1.w;
        *(float4*)&Bs[0][bk][bseg*4] = wv;
    }
    __syncthreads();

    #pragma unroll 1
    for (int it=0; it<47; it++){
        int cur = it & 1, nxt = cur ^ 1;
        int ktn = k0 + (it+1)*16;
        float4 v0, v1, wv;
        bool more = (it < 46);
        if (more){
            v0 = *(const float4*)(a0p + ktn);
            v1 = *(const float4*)(a1p + ktn);
            wv = *(const float4*)(bp + ktn*64);
        }
        #pragma unroll
        for (int k=0;k<16;k++){
            const float* ar = &As[cur][k][ty*8];
            unsigned long long a0 = *(const unsigned long long*)(ar+0);
            unsigned long long a1 = *(const unsigned long long*)(ar+2);
            unsigned long long a2 = *(const unsigned long long*)(ar+4);
            unsigned long long a3 = *(const unsigned long long*)(ar+6);
            float4 bv = *(const float4*)&Bs[cur][k][tx*4];
            unsigned long long b0,b1,b2,b3;
            asm("mov.b64 %0, {%1, %1};" : "=l"(b0) : "r"(__float_as_uint(bv.x)));
            asm("mov.b64 %0, {%1, %1};" : "=l"(b1) : "r"(__float_as_uint(bv.y)));
            asm("mov.b64 %0, {%1, %1};" : "=l"(b2) : "r"(__float_as_uint(bv.z)));
            asm("mov.b64 %0, {%1, %1};" : "=l"(b3) : "r"(__float_as_uint(bv.w)));
            FMA2(acc[0][0], a0, b0); FMA2(acc[0][1], a0, b1);
            FMA2(acc[0][2], a0, b2); FMA2(acc[0][3], a0, b3);
            FMA2(acc[1][0], a1, b0); FMA2(acc[1][1], a1, b1);
            FMA2(acc[1][2], a1, b2); FMA2(acc[1][3], a1, b3);
            FMA2(acc[2][0], a2, b0); FMA2(acc[2][1], a2, b1);
            FMA2(acc[2][2], a2, b2); FMA2(acc[2][3], a2, b3);
            FMA2(acc[3][0], a3, b0); FMA2(acc[3][1], a3, b1);
            FMA2(acc[3][2], a3, b2); FMA2(acc[3][3], a3, b3);
        }
        if (more){
            As[nxt][aseg*4+0][arow] = v0.x; As[nxt][aseg*4+1][arow] = v0.y;
            As[nxt][aseg*4+2][arow] = v0.z; As[nxt][aseg*4+3][arow] = v0.w;
            As[nxt][aseg*4+0][64+arow] = v1.x; As[nxt][aseg*4+1][64+arow] = v1.y;
            As[nxt][aseg*4+2][64+arow] = v1.z; As[nxt][aseg*4+3][64+arow] = v1.w;
            *(float4*)&Bs[nxt][bk][bseg*4] = wv;
            __syncthreads();
        }
    }
    float* dst = h ? g_o1b : g_o1a;
    #pragma unroll
    for (int j=0;j<4;j++){
        int o = tx*4 + j;
        float bb = h ? 0.f : g_bias[o];
        #pragma unroll
        for (int i=0;i<4;i++){
            float lo = __uint_as_float((unsigned)(acc[i][j] & 0xffffffffULL));
            float hi = __uint_as_float((unsigned)(acc[i][j] >> 32));
            *(float2*)&dst[o*NP + p0 + ty*8 + i*2] = make_float2(lo+bb, hi+bb);
        }
    }
}

// ---------------- BN statistics per channel (float4 reads) ----------------
__global__ void k_bnstat(const float* __restrict__ gamma,
                         const float* __restrict__ beta){
    int o = blockIdx.x, t = threadIdx.x;
    const float4* ra = (const float4*)(g_o1a + o*NP);
    const float4* rb = (const float4*)(g_o1b + o*NP);
    double s = 0.0, s2 = 0.0;
    for (int i=t; i<NP/4; i+=256){
        float4 va = ra[i], vb = rb[i];
        double v0 = (double)(va.x+vb.x), v1 = (double)(va.y+vb.y);
        double v2 = (double)(va.z+vb.z), v3 = (double)(va.w+vb.w);
        s += v0+v1+v2+v3;
        s2 += v0*v0 + v1*v1 + v2*v2 + v3*v3;
    }
    __shared__ double sh1[256], sh2[256];
    sh1[t] = s; sh2[t] = s2;
    __syncthreads();
    for (int off=128; off; off>>=1){
        if (t < off){ sh1[t] += sh1[t+off]; sh2[t] += sh2[t+off]; }
        __syncthreads();
    }
    if (t == 0){
        double mean = sh1[0] / (double)NP;
        double var  = sh2[0] / (double)NP - mean*mean;
        float sc = gamma[o] / sqrtf((float)var + 1e-5f);
        g_scale[o] = sc;
        g_shift[o] = beta[o] - (float)mean * sc;
    }
}

// ---------------- finalize: affine BN + layout [B,C,N] (float4) ----------------
__global__ void k_final(float* __restrict__ out){
    int e4 = blockIdx.x*blockDim.x + threadIdx.x;   // < 262144
    int base = e4 * 4;
    int n = base & 2047;
    int o = (base >> 11) & 63;
    int b = base >> 17;
    int idx = o*NP + b*Nn + n;
    float4 va = *(const float4*)(g_o1a + idx);
    float4 vb = *(const float4*)(g_o1b + idx);
    float sc = g_scale[o], sh = g_shift[o];
    float4 r;
    r.x = (va.x+vb.x)*sc + sh;
    r.y = (va.y+vb.y)*sc + sh;
    r.z = (va.z+vb.z)*sc + sh;
    r.w = (va.w+vb.w)*sc + sh;
    *(float4*)(out + base) = r;
}

// ---------------- launch ----------------
extern "C" void kernel_launch(void* const* d_in, const int* in_sizes, int n_in,
                              void* d_out, int out_size){
    (void)in_sizes; (void)n_in; (void)out_size;
    const float* x         = (const float*)d_in[0];
    const float* feature   = (const float*)d_in[1];
    const float* kernals   = (const float*)d_in[2];
    const float* one_pad   = (const float*)d_in[3];
    const float* mlp_w     = (const float*)d_in[4];
    const float* mlp_b     = (const float*)d_in[5];
    const float* conv_w    = (const float*)d_in[6];
    const float* conv_b    = (const float*)d_in[7];
    const float* mlp_out_w = (const float*)d_in[8];
    const float* mlp_out_b = (const float*)d_in[9];
    const float* bn_gamma  = (const float*)d_in[10];
    const float* bn_beta   = (const float*)d_in[11];
    float* out = (float*)d_out;

    k_transpose<<<dim3(Nn/32, Cin/32, Bn), dim3(32,8)>>>(feature);
    k_prepw<<<(XSTRIDE*Cout)/256, 256>>>(conv_w, mlp_w, mlp_b,
                                         mlp_out_w, conv_b, mlp_out_b);
    k_knn<<<dim3(Nn/16, Bn), 64>>>(x);
    k_point<<<NP/2, 128>>>(x, kernals, one_pad);
    k_gemm<<<dim3(NP/128, 2), 256>>>();
    k_bnstat<<<Cout, 256>>>(bn_gamma, bn_beta);
    k_final<<<(Bn*Cout*Nn)/1024, 256>>>(out);
}

// round 13
// speedup vs baseline: 1.8166x; 1.1052x over previous
#include <cuda_runtime.h>
#include <math.h>

// Problem constants
#define Bn   8
#define Nn   2048
#define Cin  64
#define Cout 64
#define Kn   20
#define KSn  20
#define NP   (Bn*Nn)      // 16384 points
#define XK   1504         // packed GEMM inner dim: 1280 agg + 160 g + 64 feat
#define XKH  752          // split-K half (47 tiles of 16)
#define XSTRIDE 1536      // padded row stride (float4 aligned)

#define KNN_SMEM ((3*Nn + 4*Nn)*sizeof(float))   // 57344 B

// ---------------- scratch (__device__ globals, no allocation) ----------------
__device__ float g_Ft[NP*Cin];            // feature transposed [p][c]   (4 MB)
__device__ int   g_idx[NP*Kn];            // knn indices                 (1.3 MB)
__device__ float g_X[(size_t)NP*XSTRIDE]; // packed per-point vectors    (100 MB)
__device__ float g_Wt[XSTRIDE*Cout];      // packed weights [k][o]
__device__ float g_bias[Cout];
__device__ float g_o1a[Cout*NP];          // pre-BN output half A [o][p] (4 MB)
__device__ float g_o1b[Cout*NP];          // pre-BN output half B [o][p] (4 MB)
__device__ float g_scale[Cout];
__device__ float g_shift[Cout];

// packed f32x2 FMA: d = a*b + d  (two fp32 lanes per instruction)
#define FMA2(d, a, b) \
    asm("fma.rn.f32x2 %0, %1, %2, %0;" : "+l"(d) : "l"(a), "l"(b))

// ---------------- feature transpose: [B,C,N] -> [B*N, C] ----------------
__global__ void k_transpose(const float* __restrict__ f){
    __shared__ float tile[32][33];
    int b = blockIdx.z, c0 = blockIdx.y*32, n0 = blockIdx.x*32;
    int tx = threadIdx.x, ty = threadIdx.y;
    #pragma unroll
    for (int i=0;i<4;i++)
        tile[ty+8*i][tx] = f[b*Cin*Nn + (c0+ty+8*i)*Nn + n0+tx];
    __syncthreads();
    #pragma unroll
    for (int i=0;i<4;i++)
        g_Ft[(b*Nn + n0+ty+8*i)*Cin + c0+tx] = tile[tx][ty+8*i];
}

// ---------------- pack weights Wt[k][o] ----------------
// agg block is m-major: X position q (q<1280) holds agg[c][m], c=q&63, m=q>>6
__global__ void k_prepw(const float* __restrict__ conv_w,
                        const float* __restrict__ mlp_w,
                        const float* __restrict__ mlp_b,
                        const float* __restrict__ mlp_out_w){
    int id = blockIdx.x*blockDim.x + threadIdx.x;   // < 1536*64
    int k = id >> 6, o = id & 63;
    float v = 0.f;
    if (k < 1280){
        int c = k & 63, m = k >> 6;
        v = conv_w[o*2560 + c*KSn + m];
    } else if (k < 1440){
        int e = k - 1280;
        int m = e >> 3, j = e & 7;
        const float* cw = conv_w + o*2560 + 1280 + m;   // (64+c2)*20+m
        float s = 0.f;
        if (j < 7){
            for (int c2=0;c2<64;c2++) s += mlp_w[c2*7+j]*cw[c2*20];
        } else {
            for (int c2=0;c2<64;c2++) s += mlp_b[c2]*cw[c2*20];
        }
        v = s;
    } else if (k < XK){
        v = mlp_out_w[o*64 + (k-1440)];
    }
    g_Wt[k*64 + o] = v;
}

// ---------------- fused bias ----------------
__global__ void k_prepb(const float* __restrict__ conv_b,
                        const float* __restrict__ mlp_out_b){
    int o = threadIdx.x;
    g_bias[o] = conv_b[o] + mlp_out_b[o];
}

// ---------------- KNN: warp per query, min-extraction top-20 ----------------
// 4 warps per block share the point tile; per-warp 8 KB distance arrays.
// argmin via redux.sync.min.u32 (positive fp32 bits are order-isomorphic)
__global__ void __launch_bounds__(128) k_knn(const float* __restrict__ x){
    extern __shared__ float sh[];
    float* spx = sh;
    float* spy = sh +   Nn;
    float* spz = sh + 2*Nn;
    int t = threadIdx.x, w = t>>5, lane = t&31;
    int b = blockIdx.y;
    const float* xb = x + b*3*Nn;
    for (int e=t; e<Nn; e+=128){
        spx[e] = xb[e]; spy[e] = xb[Nn+e]; spz[e] = xb[2*Nn+e];
    }
    __syncthreads();
    float* sd = sh + 3*Nn + w*Nn;

    for (int i=0;i<8;i++){
        int q = blockIdx.x*32 + w*8 + i;
        float qx = spx[q], qy = spy[q], qz = spz[q];
        float mn = 3.0e38f; int amn = 0;
        #pragma unroll 8
        for (int tt=0; tt<64; tt++){
            int j = lane + (tt<<5);
            float dx = spx[j]-qx, dy = spy[j]-qy, dz = spz[j]-qz;
            float d2 = dx*dx + dy*dy + dz*dz;
            sd[j ^ (tt & 31)] = d2;
            if (d2 < mn){ mn = d2; amn = j; }
        }
        __syncwarp();
        int myn = 0;
        for (int kk=0; kk<Kn; kk++){
            unsigned rb_ = __reduce_min_sync(0xffffffffu, __float_as_uint(mn));
            unsigned bmsk = __ballot_sync(0xffffffffu, __float_as_uint(mn)==rb_);
            int src = __ffs(bmsk) - 1;
            int jst = __shfl_sync(0xffffffffu, amn, src);
            if (lane == kk) myn = jst;
            int L = jst & 31;
            if (lane == L) sd[jst ^ ((jst>>5)&31)] = 3.0e38f;
            __syncwarp();
            int j1 = L + (lane<<5);
            int j2 = L + ((lane+32)<<5);
            float v1 = sd[j1 ^ lane];
            float v2 = sd[j2 ^ lane];
            float nv; int na;
            if (v1 <= v2){ nv = v1; na = j1; } else { nv = v2; na = j2; }
            unsigned rb2 = __reduce_min_sync(0xffffffffu, __float_as_uint(nv));
            unsigned bm2 = __ballot_sync(0xffffffffu, __float_as_uint(nv)==rb2);
            int src2 = __ffs(bm2) - 1;
            int na2 = __shfl_sync(0xffffffffu, na, src2);
            if (lane == L){ mn = __uint_as_float(rb2); amn = na2; }
            __syncwarp();
        }
        if (lane < Kn) g_idx[(b*Nn + q)*Kn + lane] = myn;
    }
}

// ---------------- per-point: perm + agg + g-vector ----------------
__global__ void k_point(const float* __restrict__ x,
                        const float* __restrict__ kern,
                        const float* __restrict__ onepad){
    __shared__ int   sidx[2][Kn];
    __shared__ float sSelf[2][3];
    __shared__ float srel[2][Kn][3];
    __shared__ float sdst[2][Kn];
    __shared__ __align__(16) float sP[2][Kn][24];
    __shared__ float scol[2][KSn];

    int t = threadIdx.x;
    int half = t >> 6, u = t & 63;
    int p = blockIdx.x*2 + half;
    int b = p >> 11, n = p & 2047;
    float* xrow = g_X + (size_t)p*XSTRIDE;

    if (u < Kn) sidx[half][u] = g_idx[p*Kn + u];
    if (u < 3)  sSelf[half][u] = x[b*3*Nn + u*Nn + n];
    __syncthreads();

    if (u < Kn){
        int j = sidx[half][u];
        float rx = x[b*3*Nn +        j] - sSelf[half][0];
        float ry = x[b*3*Nn +   Nn + j] - sSelf[half][1];
        float rz = x[b*3*Nn + 2*Nn + j] - sSelf[half][2];
        srel[half][u][0] = rx; srel[half][u][1] = ry; srel[half][u][2] = rz;
        sdst[half][u] = sqrtf(rx*rx + ry*ry + rz*rz + 1e-12f);
    }
    // self feature row directly to g_X
    xrow[1440 + u] = g_Ft[p*Cin + u];
    __syncthreads();

    // raw perm = relu(rel @ kernals + one_padding)
    #pragma unroll
    for (int e=u; e<Kn*KSn; e+=64){
        int k = e/KSn, m = e - k*KSn;
        float s = srel[half][k][0]*kern[m] + srel[half][k][1]*kern[KSn+m]
                + srel[half][k][2]*kern[2*KSn+m] + onepad[e];
        sP[half][k][m] = fmaxf(s, 0.f);
    }
    __syncthreads();

    // double normalization over k + threshold, per column m
    if (u < KSn){
        float s1 = 0.f;
        #pragma unroll
        for (int k=0;k<Kn;k++) s1 += sP[half][k][u];
        float inv1 = 1.f/(s1 + 1e-6f);
        float v[Kn]; float s2 = 0.f;
        #pragma unroll
        for (int k=0;k<Kn;k++){ float q = sP[half][k][u]*inv1; q = q*q; v[k] = q; s2 += q; }
        float inv2 = 1.f/(s2 + 1e-6f);
        float s3 = 0.f;
        #pragma unroll
        for (int k=0;k<Kn;k++){
            float q = v[k]*inv2;
            q = (q > 0.1f) ? q : 0.f;
            sP[half][k][u] = q; s3 += q;
        }
        scol[half][u] = s3;
    }
    __syncthreads();

    // g[m][j]: x-path compressed to 8 components per m, direct STG
    #pragma unroll
    for (int e=u; e<160; e+=64){
        int m = e>>3, j = e&7;
        float val;
        if (j < 3) val = sSelf[half][j]*scol[half][m];
        else if (j == 7) val = scol[half][m];
        else if (j == 6){
            float s = 0.f;
            #pragma unroll
            for (int k=0;k<Kn;k++) s += sdst[half][k]*sP[half][k][m];
            val = s;
        } else {
            float s = 0.f;
            #pragma unroll
            for (int k=0;k<Kn;k++) s += srel[half][k][j-3]*sP[half][k][m];
            val = s;
        }
        xrow[1280 + m*8 + j] = val;
    }

    // agg[c][m] = sum_k NF[k][c]*P[k][m]; thread u = channel c, all 20 m.
    {
        const int base = b*Nn;
        float acc[20];
        #pragma unroll
        for (int i=0;i<20;i++) acc[i] = 0.f;
        #pragma unroll
        for (int k=0;k<Kn;k++){
            float vv = g_Ft[(size_t)(base + sidx[half][k])*Cin + u];
            const float4* pr = (const float4*)sP[half][k];
            float4 q0 = pr[0], q1 = pr[1], q2 = pr[2], q3 = pr[3], q4 = pr[4];
            acc[0]+=vv*q0.x;  acc[1]+=vv*q0.y;  acc[2]+=vv*q0.z;  acc[3]+=vv*q0.w;
            acc[4]+=vv*q1.x;  acc[5]+=vv*q1.y;  acc[6]+=vv*q1.z;  acc[7]+=vv*q1.w;
            acc[8]+=vv*q2.x;  acc[9]+=vv*q2.y;  acc[10]+=vv*q2.z; acc[11]+=vv*q2.w;
            acc[12]+=vv*q3.x; acc[13]+=vv*q3.y; acc[14]+=vv*q3.z; acc[15]+=vv*q3.w;
            acc[16]+=vv*q4.x; acc[17]+=vv*q4.y; acc[18]+=vv*q4.z; acc[19]+=vv*q4.w;
        }
        #pragma unroll
        for (int m=0;m<20;m++)
            xrow[m*64 + u] = acc[m];
    }
}

// ---------------- GEMM (split-K=2, FFMA2, double-buffered smem) ----------------
// thread tile: 8 consecutive p-rows (4 packed pairs) x 4 o-columns
__global__ void __launch_bounds__(256) k_gemm(){
    __shared__ float As[2][16][132];
    __shared__ __align__(16) float Bs[2][16][64];
    int t = threadIdx.x;
    int p0 = blockIdx.x * 128;
    int h  = blockIdx.y;
    int k0 = h * XKH;
    int tx = t & 15, ty = t >> 4;
    int arow = t >> 2, aseg = t & 3;       // As loader mapping (rows 0..63 / +64)
    int bk   = t >> 4, bseg = t & 15;      // Bs loader mapping
    unsigned long long acc[4][4];
    #pragma unroll
    for (int i=0;i<4;i++)
        #pragma unroll
        for (int j=0;j<4;j++) acc[i][j] = 0ULL;

    const float* a0p = g_X + (size_t)(p0+arow)*XSTRIDE + aseg*4;
    const float* a1p = g_X + (size_t)(p0+64+arow)*XSTRIDE + aseg*4;
    const float* bp  = g_Wt + bk*64 + bseg*4;

    // preload tile 0 into buffer 0
    {
        float4 v0 = *(const float4*)(a0p + k0);
        float4 v1 = *(const float4*)(a1p + k0);
        float4 wv = *(const float4*)(bp + k0*64);
        As[0][aseg*4+0][arow] = v0.x; As[0][aseg*4+1][arow] = v0.y;
        As[0][aseg*4+2][arow] = v0.z; As[0][aseg*4+3][arow] = v0.w;
        As[0][aseg*4+0][64+arow] = v1.x; As[0][aseg*4+1][64+arow] = v1.y;
        As[0][aseg*4+2][64+arow] = v1.z; As[0][aseg*4+3][64+arow] = v1.w;
        *(float4*)&Bs[0][bk][bseg*4] = wv;
    }
    __syncthreads();

    #pragma unroll 1
    for (int it=0; it<47; it++){
        int cur = it & 1, nxt = cur ^ 1;
        int ktn = k0 + (it+1)*16;
        float4 v0, v1, wv;
        bool more = (it < 46);
        if (more){
            v0 = *(const float4*)(a0p + ktn);
            v1 = *(const float4*)(a1p + ktn);
            wv = *(const float4*)(bp + ktn*64);
        }
        #pragma unroll
        for (int k=0;k<16;k++){
            const float* ar = &As[cur][k][ty*8];
            unsigned long long a0 = *(const unsigned long long*)(ar+0);
            unsigned long long a1 = *(const unsigned long long*)(ar+2);
            unsigned long long a2 = *(const unsigned long long*)(ar+4);
            unsigned long long a3 = *(const unsigned long long*)(ar+6);
            float4 bv = *(const float4*)&Bs[cur][k][tx*4];
            unsigned long long b0,b1,b2,b3;
            asm("mov.b64 %0, {%1, %1};" : "=l"(b0) : "r"(__float_as_uint(bv.x)));
            asm("mov.b64 %0, {%1, %1};" : "=l"(b1) : "r"(__float_as_uint(bv.y)));
            asm("mov.b64 %0, {%1, %1};" : "=l"(b2) : "r"(__float_as_uint(bv.z)));
            asm("mov.b64 %0, {%1, %1};" : "=l"(b3) : "r"(__float_as_uint(bv.w)));
            FMA2(acc[0][0], a0, b0); FMA2(acc[0][1], a0, b1);
            FMA2(acc[0][2], a0, b2); FMA2(acc[0][3], a0, b3);
            FMA2(acc[1][0], a1, b0); FMA2(acc[1][1], a1, b1);
            FMA2(acc[1][2], a1, b2); FMA2(acc[1][3], a1, b3);
            FMA2(acc[2][0], a2, b0); FMA2(acc[2][1], a2, b1);
            FMA2(acc[2][2], a2, b2); FMA2(acc[2][3], a2, b3);
            FMA2(acc[3][0], a3, b0); FMA2(acc[3][1], a3, b1);
            FMA2(acc[3][2], a3, b2); FMA2(acc[3][3], a3, b3);
        }
        if (more){
            As[nxt][aseg*4+0][arow] = v0.x; As[nxt][aseg*4+1][arow] = v0.y;
            As[nxt][aseg*4+2][arow] = v0.z; As[nxt][aseg*4+3][arow] = v0.w;
            As[nxt][aseg*4+0][64+arow] = v1.x; As[nxt][aseg*4+1][64+arow] = v1.y;
            As[nxt][aseg*4+2][64+arow] = v1.z; As[nxt][aseg*4+3][64+arow] = v1.w;
            *(float4*)&Bs[nxt][bk][bseg*4] = wv;
            __syncthreads();
        }
    }
    float* dst = h ? g_o1b : g_o1a;
    #pragma unroll
    for (int j=0;j<4;j++){
        int o = tx*4 + j;
        float bb = h ? 0.f : g_bias[o];
        #pragma unroll
        for (int i=0;i<4;i++){
            float lo = __uint_as_float((unsigned)(acc[i][j] & 0xffffffffULL));
            float hi = __uint_as_float((unsigned)(acc[i][j] >> 32));
            *(float2*)&dst[o*NP + p0 + ty*8 + i*2] = make_float2(lo+bb, hi+bb);
        }
    }
}

// ---------------- BN statistics per channel (float4 reads) ----------------
__global__ void k_bnstat(const float* __restrict__ gamma,
                         const float* __restrict__ beta){
    int o = blockIdx.x, t = threadIdx.x;
    const float4* ra = (const float4*)(g_o1a + o*NP);
    const float4* rb = (const float4*)(g_o1b + o*NP);
    double s = 0.0, s2 = 0.0;
    for (int i=t; i<NP/4; i+=256){
        float4 va = ra[i], vb = rb[i];
        double v0 = (double)(va.x+vb.x), v1 = (double)(va.y+vb.y);
        double v2 = (double)(va.z+vb.z), v3 = (double)(va.w+vb.w);
        s += v0+v1+v2+v3;
        s2 += v0*v0 + v1*v1 + v2*v2 + v3*v3;
    }
    __shared__ double sh1[256], sh2[256];
    sh1[t] = s; sh2[t] = s2;
    __syncthreads();
    for (int off=128; off; off>>=1){
        if (t < off){ sh1[t] += sh1[t+off]; sh2[t] += sh2[t+off]; }
        __syncthreads();
    }
    if (t == 0){
        double mean = sh1[0] / (double)NP;
        double var  = sh2[0] / (double)NP - mean*mean;
        float sc = gamma[o] / sqrtf((float)var + 1e-5f);
        g_scale[o] = sc;
        g_shift[o] = beta[o] - (float)mean * sc;
    }
}

// ---------------- finalize: affine BN + layout [B,C,N] (float4) ----------------
__global__ void k_final(float* __restrict__ out){
    int e4 = blockIdx.x*blockDim.x + threadIdx.x;   // < 262144
    int base = e4 * 4;
    int n = base & 2047;
    int o = (base >> 11) & 63;
    int b = base >> 17;
    int idx = o*NP + b*Nn + n;
    float4 va = *(const float4*)(g_o1a + idx);
    float4 vb = *(const float4*)(g_o1b + idx);
    float sc = g_scale[o], sh = g_shift[o];
    float4 r;
    r.x = (va.x+vb.x)*sc + sh;
    r.y = (va.y+vb.y)*sc + sh;
    r.z = (va.z+vb.z)*sc + sh;
    r.w = (va.w+vb.w)*sc + sh;
    *(float4*)(out + base) = r;
}

// ---------------- launch ----------------
extern "C" void kernel_launch(void* const* d_in, const int* in_sizes, int n_in,
                              void* d_out, int out_size){
    (void)in_sizes; (void)n_in; (void)out_size;
    const float* x         = (const float*)d_in[0];
    const float* feature   = (const float*)d_in[1];
    const float* kernals   = (const float*)d_in[2];
    const float* one_pad   = (const float*)d_in[3];
    const float* mlp_w     = (const float*)d_in[4];
    const float* mlp_b     = (const float*)d_in[5];
    const float* conv_w    = (const float*)d_in[6];
    const float* conv_b    = (const float*)d_in[7];
    const float* mlp_out_w = (const float*)d_in[8];
    const float* mlp_out_b = (const float*)d_in[9];
    const float* bn_gamma  = (const float*)d_in[10];
    const float* bn_beta   = (const float*)d_in[11];
    float* out = (float*)d_out;

    cudaFuncSetAttribute(k_knn, cudaFuncAttributeMaxDynamicSharedMemorySize,
                         (int)KNN_SMEM);

    k_transpose<<<dim3(Nn/32, Cin/32, Bn), dim3(32,8)>>>(feature);
    k_prepw<<<(XSTRIDE*Cout)/256, 256>>>(conv_w, mlp_w, mlp_b, mlp_out_w);
    k_prepb<<<1, 64>>>(conv_b, mlp_out_b);
    k_knn<<<dim3(Nn/32, Bn), 128, KNN_SMEM>>>(x);
    k_point<<<NP/2, 128>>>(x, kernals, one_pad);
    k_gemm<<<dim3(NP/128, 2), 256>>>();
    k_bnstat<<<Cout, 256>>>(bn_gamma, bn_beta);
    k_final<<<(Bn*Cout*Nn)/1024, 256>>>(out);
}

// round 15
// speedup vs baseline: 1.9501x; 1.0735x over previous
#include <cuda_runtime.h>
#include <math.h>

// Problem constants
#define Bn   8
#define Nn   2048
#define Cin  64
#define Cout 64
#define Kn   20
#define KSn  20
#define NP   (Bn*Nn)      // 16384 points
#define XK   1504         // packed GEMM inner dim: 1280 agg + 160 g + 64 feat
#define XKH  752          // split-K half (47 tiles of 16)
#define XSTRIDE 1536      // padded row stride (float4 aligned)

#define KNN_SMEM ((3*Nn + 4*Nn)*sizeof(float))   // 57344 B

// ---------------- scratch (__device__ globals, no allocation) ----------------
__device__ float g_Ft[NP*Cin];            // feature transposed [p][c]   (4 MB)
__device__ int   g_idx[NP*Kn];            // knn indices                 (1.3 MB)
__device__ float g_X[(size_t)NP*XSTRIDE]; // packed per-point vectors    (100 MB)
__device__ float g_Wt[XSTRIDE*Cout];      // packed weights [k][o]
__device__ float g_bias[Cout];
__device__ float g_o1a[Cout*NP];          // pre-BN output half A [o][p] (4 MB)
__device__ float g_o1b[Cout*NP];          // pre-BN output half B [o][p] (4 MB)
__device__ float g_scale[Cout];
__device__ float g_shift[Cout];

// packed f32x2 FMA: d = a*b + d  (two fp32 lanes per instruction)
#define FMA2(d, a, b) \
    asm("fma.rn.f32x2 %0, %1, %2, %0;" : "+l"(d) : "l"(a), "l"(b))

// ---------------- feature transpose: [B,C,N] -> [B*N, C] ----------------
__global__ void k_transpose(const float* __restrict__ f){
    __shared__ float tile[32][33];
    int b = blockIdx.z, c0 = blockIdx.y*32, n0 = blockIdx.x*32;
    int tx = threadIdx.x, ty = threadIdx.y;
    #pragma unroll
    for (int i=0;i<4;i++)
        tile[ty+8*i][tx] = f[b*Cin*Nn + (c0+ty+8*i)*Nn + n0+tx];
    __syncthreads();
    #pragma unroll
    for (int i=0;i<4;i++)
        g_Ft[(b*Nn + n0+ty+8*i)*Cin + c0+tx] = tile[tx][ty+8*i];
}

// ---------------- pack weights Wt[k][o] ----------------
// agg block is m-major: X position q (q<1280) holds agg[c][m], c=q&63, m=q>>6
__global__ void k_prepw(const float* __restrict__ conv_w,
                        const float* __restrict__ mlp_w,
                        const float* __restrict__ mlp_b,
                        const float* __restrict__ mlp_out_w){
    int id = blockIdx.x*blockDim.x + threadIdx.x;   // < 1536*64
    int k = id >> 6, o = id & 63;
    float v = 0.f;
    if (k < 1280){
        int c = k & 63, m = k >> 6;
        v = conv_w[o*2560 + c*KSn + m];
    } else if (k < 1440){
        int e = k - 1280;
        int m = e >> 3, j = e & 7;
        const float* cw = conv_w + o*2560 + 1280 + m;   // (64+c2)*20+m
        float s = 0.f;
        if (j < 7){
            for (int c2=0;c2<64;c2++) s += mlp_w[c2*7+j]*cw[c2*20];
        } else {
            for (int c2=0;c2<64;c2++) s += mlp_b[c2]*cw[c2*20];
        }
        v = s;
    } else if (k < XK){
        v = mlp_out_w[o*64 + (k-1440)];
    }
    g_Wt[k*64 + o] = v;
}

// ---------------- fused bias ----------------
__global__ void k_prepb(const float* __restrict__ conv_b,
                        const float* __restrict__ mlp_out_b){
    int o = threadIdx.x;
    g_bias[o] = conv_b[o] + mlp_out_b[o];
}

// ---------------- KNN: warp per query, top-2 lane cache + lazy rescan ----------
// Exact top-20 set: every extracted candidate's sd slot is invalidated, so a
// rescan sees exactly the un-extracted remainder of the owner's 64 slots.
__global__ void __launch_bounds__(128) k_knn(const float* __restrict__ x){
    extern __shared__ float sh[];
    float* spx = sh;
    float* spy = sh +   Nn;
    float* spz = sh + 2*Nn;
    int t = threadIdx.x, w = t>>5, lane = t&31;
    int b = blockIdx.y;
    const float* xb = x + b*3*Nn;
    for (int e=t; e<Nn; e+=128){
        spx[e] = xb[e]; spy[e] = xb[Nn+e]; spz[e] = xb[2*Nn+e];
    }
    __syncthreads();
    float* sd = sh + 3*Nn + w*Nn;
    const unsigned INFU = 0x7F800000u;
    const float INFV = __uint_as_float(INFU);

    for (int i=0;i<8;i++){
        int q = blockIdx.x*32 + w*8 + i;
        float qx = spx[q], qy = spy[q], qz = spz[q];
        float m1 = INFV, m2 = INFV; int a1 = 0, a2 = 0;
        #pragma unroll 8
        for (int tt=0; tt<64; tt++){
            int j = lane + (tt<<5);
            float dx = spx[j]-qx, dy = spy[j]-qy, dz = spz[j]-qz;
            float d2 = dx*dx + dy*dy + dz*dz;
            sd[j ^ (tt & 31)] = d2;
            if (d2 < m1){ m2=m1; a2=a1; m1=d2; a1=j; }
            else if (d2 < m2){ m2=d2; a2=j; }
        }
        __syncwarp();
        int myn = 0;
        for (int kk=0; kk<Kn; kk++){
            unsigned gm = __reduce_min_sync(0xffffffffu, __float_as_uint(m1));
            unsigned bm = __ballot_sync(0xffffffffu, __float_as_uint(m1)==gm);
            int L = __ffs(bm) - 1;
            int jst = __shfl_sync(0xffffffffu, a1, L);
            if (lane == kk) myn = jst;
            if (lane == L){
                sd[jst ^ ((jst>>5)&31)] = INFV;   // invalidate extracted slot
                m1 = m2; a1 = a2; m2 = INFV;      // pop register cache
            }
            // lazy rescan when the owner's cache is exhausted
            unsigned rs = __ballot_sync(0xffffffffu,
                          (lane==L) && (__float_as_uint(m1)==INFU));
            if (rs){
                __syncwarp();   // invalidation visible before cooperative loads
                int j1 = L + (lane<<5);
                int j2 = L + ((lane+32)<<5);
                float v1 = sd[j1 ^ lane];
                float v2 = sd[j2 ^ lane];
                float nv; int na;
                if (v1 <= v2){ nv = v1; na = j1; } else { nv = v2; na = j2; }
                unsigned r2 = __reduce_min_sync(0xffffffffu, __float_as_uint(nv));
                unsigned b2 = __ballot_sync(0xffffffffu, __float_as_uint(nv)==r2);
                int s2 = __ffs(b2) - 1;
                int na2 = __shfl_sync(0xffffffffu, na, s2);
                if (lane == L){ m1 = __uint_as_float(r2); a1 = na2; }
            }
            __syncwarp();
        }
        if (lane < Kn) g_idx[(b*Nn + q)*Kn + lane] = myn;
    }
}

// ---------------- per-point: perm + agg + g fused into dnorm ----------------
__global__ void k_point(const float* __restrict__ x,
                        const float* __restrict__ kern,
                        const float* __restrict__ onepad){
    __shared__ int   sidx[2][Kn];
    __shared__ float sSelf[2][3];
    __shared__ __align__(16) float4 sR4[2][Kn];     // (rx,ry,rz,dist)
    __shared__ __align__(16) float sP[2][Kn][24];

    int t = threadIdx.x;
    int half = t >> 6, u = t & 63;
    int p = blockIdx.x*2 + half;
    int b = p >> 11, n = p & 2047;
    float* xrow = g_X + (size_t)p*XSTRIDE;

    if (u < Kn) sidx[half][u] = g_idx[p*Kn + u];
    if (u < 3)  sSelf[half][u] = x[b*3*Nn + u*Nn + n];
    __syncthreads();

    if (u < Kn){
        int j = sidx[half][u];
        float rx = x[b*3*Nn +        j] - sSelf[half][0];
        float ry = x[b*3*Nn +   Nn + j] - sSelf[half][1];
        float rz = x[b*3*Nn + 2*Nn + j] - sSelf[half][2];
        float d  = sqrtf(rx*rx + ry*ry + rz*rz + 1e-12f);
        sR4[half][u] = make_float4(rx, ry, rz, d);
    }
    // self feature row directly to g_X
    xrow[1440 + u] = g_Ft[p*Cin + u];
    __syncthreads();

    // raw perm = relu(rel @ kernals + one_padding)
    #pragma unroll
    for (int e=u; e<Kn*KSn; e+=64){
        int k = e/KSn, m = e - k*KSn;
        float4 r = sR4[half][k];
        float s = r.x*kern[m] + r.y*kern[KSn+m]
                + r.z*kern[2*KSn+m] + onepad[e];
        sP[half][k][m] = fmaxf(s, 0.f);
    }
    __syncthreads();

    // double normalization over k + threshold (column m=u), fused g-vector
    if (u < KSn){
        float s1 = 0.f;
        #pragma unroll
        for (int k=0;k<Kn;k++) s1 += sP[half][k][u];
        float inv1 = 1.f/(s1 + 1e-6f);
        float v[Kn]; float s2 = 0.f;
        #pragma unroll
        for (int k=0;k<Kn;k++){ float q = sP[half][k][u]*inv1; q = q*q; v[k] = q; s2 += q; }
        float inv2 = 1.f/(s2 + 1e-6f);
        float s3 = 0.f;
        float g3 = 0.f, g4 = 0.f, g5 = 0.f, g6 = 0.f;
        #pragma unroll
        for (int k=0;k<Kn;k++){
            float q = v[k]*inv2;
            q = (q > 0.1f) ? q : 0.f;
            sP[half][k][u] = q; s3 += q;
            float4 r = sR4[half][k];
            g3 += r.x*q; g4 += r.y*q; g5 += r.z*q; g6 += r.w*q;
        }
        float sx = sSelf[half][0]*s3;
        float sy = sSelf[half][1]*s3;
        float sz = sSelf[half][2]*s3;
        float4* gx = (float4*)(xrow + 1280 + u*8);
        gx[0] = make_float4(sx, sy, sz, g3);
        gx[1] = make_float4(g4, g5, g6, s3);
    }
    __syncthreads();

    // agg[c][m] = sum_k NF[k][c]*P[k][m]; thread u = channel c, all 20 m.
    {
        const int base = b*Nn;
        float acc[20];
        #pragma unroll
        for (int i=0;i<20;i++) acc[i] = 0.f;
        #pragma unroll
        for (int k=0;k<Kn;k++){
            float vv = g_Ft[(size_t)(base + sidx[half][k])*Cin + u];
            const float4* pr = (const float4*)sP[half][k];
            float4 q0 = pr[0], q1 = pr[1], q2 = pr[2], q3 = pr[3], q4 = pr[4];
            acc[0]+=vv*q0.x;  acc[1]+=vv*q0.y;  acc[2]+=vv*q0.z;  acc[3]+=vv*q0.w;
            acc[4]+=vv*q1.x;  acc[5]+=vv*q1.y;  acc[6]+=vv*q1.z;  acc[7]+=vv*q1.w;
            acc[8]+=vv*q2.x;  acc[9]+=vv*q2.y;  acc[10]+=vv*q2.z; acc[11]+=vv*q2.w;
            acc[12]+=vv*q3.x; acc[13]+=vv*q3.y; acc[14]+=vv*q3.z; acc[15]+=vv*q3.w;
            acc[16]+=vv*q4.x; acc[17]+=vv*q4.y; acc[18]+=vv*q4.z; acc[19]+=vv*q4.w;
        }
        #pragma unroll
        for (int m=0;m<20;m++)
            xrow[m*64 + u] = acc[m];
    }
}

// ---------------- GEMM (split-K=2, FFMA2, double-buffered smem) ----------------
// thread tile: 8 consecutive p-rows (4 packed pairs) x 4 o-columns
__global__ void __launch_bounds__(256) k_gemm(){
    __shared__ float As[2][16][132];
    __shared__ __align__(16) float Bs[2][16][64];
    int t = threadIdx.x;
    int p0 = blockIdx.x * 128;
    int h  = blockIdx.y;
    int k0 = h * XKH;
    int tx = t & 15, ty = t >> 4;
    int arow = t >> 2, aseg = t & 3;       // As loader mapping (rows 0..63 / +64)
    int bk   = t >> 4, bseg = t & 15;      // Bs loader mapping
    unsigned long long acc[4][4];
    #pragma unroll
    for (int i=0;i<4;i++)
        #pragma unroll
        for (int j=0;j<4;j++) acc[i][j] = 0ULL;

    const float* a0p = g_X + (size_t)(p0+arow)*XSTRIDE + aseg*4;
    const float* a1p = g_X + (size_t)(p0+64+arow)*XSTRIDE + aseg*4;
    const float* bp  = g_Wt + bk*64 + bseg*4;

    // preload tile 0 into buffer 0
    {
        float4 v0 = *(const float4*)(a0p + k0);
        float4 v1 = *(const float4*)(a1p + k0);
        float4 wv = *(const float4*)(bp + k0*64);
        As[0][aseg*4+0][arow] = v0.x; As[0][aseg*4+1][arow] = v0.y;
        As[0][aseg*4+2][arow] = v0.z; As[0][aseg*4+3][arow] = v0.w;
        As[0][aseg*4+0][64+arow] = v1.x; As[0][aseg*4+1][64+arow] = v1.y;
        As[0][aseg*4+2][64+arow] = v1.z; As[0][aseg*4+3][64+arow] = v1.w;
        *(float4*)&Bs[0][bk][bseg*4] = wv;
    }
    __syncthreads();

    #pragma unroll 1
    for (int it=0; it<47; it++){
        int cur = it & 1, nxt = cur ^ 1;
        int ktn = k0 + (it+1)*16;
        float4 v0, v1, wv;
        bool more = (it < 46);
        if (more){
            v0 = *(const float4*)(a0p + ktn);
            v1 = *(const float4*)(a1p + ktn);
            wv = *(const float4*)(bp + ktn*64);
        }
        #pragma unroll
        for (int k=0;k<16;k++){
            const float* ar = &As[cur][k][ty*8];
            unsigned long long a0 = *(const unsigned long long*)(ar+0);
            unsigned long long a1 = *(const unsigned long long*)(ar+2);
            unsigned long long a2 = *(const unsigned long long*)(ar+4);
            unsigned long long a3 = *(const unsigned long long*)(ar+6);
            float4 bv = *(const float4*)&Bs[cur][k][tx*4];
            unsigned long long b0,b1,b2,b3;
            asm("mov.b64 %0, {%1, %1};" : "=l"(b0) : "r"(__float_as_uint(bv.x)));
            asm("mov.b64 %0, {%1, %1};" : "=l"(b1) : "r"(__float_as_uint(bv.y)));
            asm("mov.b64 %0, {%1, %1};" : "=l"(b2) : "r"(__float_as_uint(bv.z)));
            asm("mov.b64 %0, {%1, %1};" : "=l"(b3) : "r"(__float_as_uint(bv.w)));
            FMA2(acc[0][0], a0, b0); FMA2(acc[0][1], a0, b1);
            FMA2(acc[0][2], a0, b2); FMA2(acc[0][3], a0, b3);
            FMA2(acc[1][0], a1, b0); FMA2(acc[1][1], a1, b1);
            FMA2(acc[1][2], a1, b2); FMA2(acc[1][3], a1, b3);
            FMA2(acc[2][0], a2, b0); FMA2(acc[2][1], a2, b1);
            FMA2(acc[2][2], a2, b2); FMA2(acc[2][3], a2, b3);
            FMA2(acc[3][0], a3, b0); FMA2(acc[3][1], a3, b1);
            FMA2(acc[3][2], a3, b2); FMA2(acc[3][3], a3, b3);
        }
        if (more){
            As[nxt][aseg*4+0][arow] = v0.x; As[nxt][aseg*4+1][arow] = v0.y;
            As[nxt][aseg*4+2][arow] = v0.z; As[nxt][aseg*4+3][arow] = v0.w;
            As[nxt][aseg*4+0][64+arow] = v1.x; As[nxt][aseg*4+1][64+arow] = v1.y;
            As[nxt][aseg*4+2][64+arow] = v1.z; As[nxt][aseg*4+3][64+arow] = v1.w;
            *(float4*)&Bs[nxt][bk][bseg*4] = wv;
            __syncthreads();
        }
    }
    float* dst = h ? g_o1b : g_o1a;
    #pragma unroll
    for (int j=0;j<4;j++){
        int o = tx*4 + j;
        float bb = h ? 0.f : g_bias[o];
        #pragma unroll
        for (int i=0;i<4;i++){
            float lo = __uint_as_float((unsigned)(acc[i][j] & 0xffffffffULL));
            float hi = __uint_as_float((unsigned)(acc[i][j] >> 32));
            *(float2*)&dst[o*NP + p0 + ty*8 + i*2] = make_float2(lo+bb, hi+bb);
        }
    }
}

// ---------------- BN statistics per channel (float4 reads) ----------------
__global__ void k_bnstat(const float* __restrict__ gamma,
                         const float* __restrict__ beta){
    int o = blockIdx.x, t = threadIdx.x;
    const float4* ra = (const float4*)(g_o1a + o*NP);
    const float4* rb = (const float4*)(g_o1b + o*NP);
    double s = 0.0, s2 = 0.0;
    for (int i=t; i<NP/4; i+=256){
        float4 va = ra[i], vb = rb[i];
        double v0 = (double)(va.x+vb.x), v1 = (double)(va.y+vb.y);
        double v2 = (double)(va.z+vb.z), v3 = (double)(va.w+vb.w);
        s += v0+v1+v2+v3;
        s2 += v0*v0 + v1*v1 + v2*v2 + v3*v3;
    }
    __shared__ double sh1[256], sh2[256];
    sh1[t] = s; sh2[t] = s2;
    __syncthreads();
    for (int off=128; off; off>>=1){
        if (t < off){ sh1[t] += sh1[t+off]; sh2[t] += sh2[t+off]; }
        __syncthreads();
    }
    if (t == 0){
        double mean = sh1[0] / (double)NP;
        double var  = sh2[0] / (double)NP - mean*mean;
        float sc = gamma[o] / sqrtf((float)var + 1e-5f);
        g_scale[o] = sc;
        g_shift[o] = beta[o] - (float)mean * sc;
    }
}

// ---------------- finalize: affine BN + layout [B,C,N] (float4) ----------------
__global__ void k_final(float* __restrict__ out){
    int e4 = blockIdx.x*blockDim.x + threadIdx.x;   // < 262144
    int base = e4 * 4;
    int n = base & 2047;
    int o = (base >> 11) & 63;
    int b = base >> 17;
    int idx = o*NP + b*Nn + n;
    float4 va = *(const float4*)(g_o1a + idx);
    float4 vb = *(const float4*)(g_o1b + idx);
    float sc = g_scale[o], sh = g_shift[o];
    float4 r;
    r.x = (va.x+vb.x)*sc + sh;
    r.y = (va.y+vb.y)*sc + sh;
    r.z = (va.z+vb.z)*sc + sh;
    r.w = (va.w+vb.w)*sc + sh;
    *(float4*)(out + base) = r;
}

// ---------------- launch ----------------
extern "C" void kernel_launch(void* const* d_in, const int* in_sizes, int n_in,
                              void* d_out, int out_size){
    (void)in_sizes; (void)n_in; (void)out_size;
    const float* x         = (const float*)d_in[0];
    const float* feature   = (const float*)d_in[1];
    const float* kernals   = (const float*)d_in[2];
    const float* one_pad   = (const float*)d_in[3];
    const float* mlp_w     = (const float*)d_in[4];
    const float* mlp_b     = (const float*)d_in[5];
    const float* conv_w    = (const float*)d_in[6];
    const float* conv_b    = (const float*)d_in[7];
    const float* mlp_out_w = (const float*)d_in[8];
    const float* mlp_out_b = (const float*)d_in[9];
    const float* bn_gamma  = (const float*)d_in[10];
    const float* bn_beta   = (const float*)d_in[11];
    float* out = (float*)d_out;

    cudaFuncSetAttribute(k_knn, cudaFuncAttributeMaxDynamicSharedMemorySize,
                         (int)KNN_SMEM);

    k_transpose<<<dim3(Nn/32, Cin/32, Bn), dim3(32,8)>>>(feature);
    k_prepw<<<(XSTRIDE*Cout)/256, 256>>>(conv_w, mlp_w, mlp_b, mlp_out_w);
    k_prepb<<<1, 64>>>(conv_b, mlp_out_b);
    k_knn<<<dim3(Nn/32, Bn), 128, KNN_SMEM>>>(x);
    k_point<<<NP/2, 128>>>(x, kernals, one_pad);
    k_gemm<<<dim3(NP/128, 2), 256>>>();
    k_bnstat<<<Cout, 256>>>(bn_gamma, bn_beta);
    k_final<<<(Bn*Cout*Nn)/1024, 256>>>(out);
}

// round 16
// speedup vs baseline: 1.9930x; 1.0220x over previous
#include <cuda_runtime.h>
#include <math.h>

// Problem constants
#define Bn   8
#define Nn   2048
#define Cin  64
#define Cout 64
#define Kn   20
#define KSn  20
#define NP   (Bn*Nn)      // 16384 points
#define XK   1504         // packed GEMM inner dim: 1280 agg + 160 g + 64 feat
#define XKH  752          // split-K half (47 tiles of 16)
#define XSTRIDE 1536      // padded row stride (float4 aligned)

// ---------------- scratch (__device__ globals, no allocation) ----------------
__device__ float g_Ft[NP*Cin];            // feature transposed [p][c]   (4 MB)
__device__ int   g_idx[NP*Kn];            // knn indices                 (1.3 MB)
__device__ float g_X[(size_t)NP*XSTRIDE]; // packed per-point vectors    (100 MB)
__device__ float g_Wt[XSTRIDE*Cout];      // packed weights [k][o]
__device__ float g_bias[Cout];
__device__ float g_o1a[Cout*NP];          // pre-BN output half A [o][p] (4 MB)
__device__ float g_o1b[Cout*NP];          // pre-BN output half B [o][p] (4 MB)
__device__ float g_scale[Cout];
__device__ float g_shift[Cout];

// packed f32x2 FMA: d = a*b + d  (two fp32 lanes per instruction)
#define FMA2(d, a, b) \
    asm("fma.rn.f32x2 %0, %1, %2, %0;" : "+l"(d) : "l"(a), "l"(b))

// ---------------- feature transpose: [B,C,N] -> [B*N, C] ----------------
__global__ void k_transpose(const float* __restrict__ f){
    __shared__ float tile[32][33];
    int b = blockIdx.z, c0 = blockIdx.y*32, n0 = blockIdx.x*32;
    int tx = threadIdx.x, ty = threadIdx.y;
    #pragma unroll
    for (int i=0;i<4;i++)
        tile[ty+8*i][tx] = f[b*Cin*Nn + (c0+ty+8*i)*Nn + n0+tx];
    __syncthreads();
    #pragma unroll
    for (int i=0;i<4;i++)
        g_Ft[(b*Nn + n0+ty+8*i)*Cin + c0+tx] = tile[tx][ty+8*i];
}

// ---------------- pack weights Wt[k][o] ----------------
// agg block is m-major: X position q (q<1280) holds agg[c][m], c=q&63, m=q>>6
__global__ void k_prepw(const float* __restrict__ conv_w,
                        const float* __restrict__ mlp_w,
                        const float* __restrict__ mlp_b,
                        const float* __restrict__ mlp_out_w){
    int id = blockIdx.x*blockDim.x + threadIdx.x;   // < 1536*64
    int k = id >> 6, o = id & 63;
    float v = 0.f;
    if (k < 1280){
        int c = k & 63, m = k >> 6;
        v = conv_w[o*2560 + c*KSn + m];
    } else if (k < 1440){
        int e = k - 1280;
        int m = e >> 3, j = e & 7;
        const float* cw = conv_w + o*2560 + 1280 + m;   // (64+c2)*20+m
        float s = 0.f;
        if (j < 7){
            for (int c2=0;c2<64;c2++) s += mlp_w[c2*7+j]*cw[c2*20];
        } else {
            for (int c2=0;c2<64;c2++) s += mlp_b[c2]*cw[c2*20];
        }
        v = s;
    } else if (k < XK){
        v = mlp_out_w[o*64 + (k-1440)];
    }
    g_Wt[k*64 + o] = v;
}

// ---------------- fused bias ----------------
__global__ void k_prepb(const float* __restrict__ conv_b,
                        const float* __restrict__ mlp_out_b){
    int o = threadIdx.x;
    g_bias[o] = conv_b[o] + mlp_out_b[o];
}

// ---------------- KNN: swizzled points, register top-2, recompute rescan ----
// Points stored bank-swizzled (pos = e ^ ((e>>5)&31)); no per-warp distance
// array. Extracted candidates tracked in a per-lane 64-bit slot mask; a
// rescan recomputes the owner's 64 candidate distances (conflict-free banks)
// excluding extracted slots — exact top-20 set.
__global__ void __launch_bounds__(128) k_knn(const float* __restrict__ x){
    __shared__ float spx[Nn];
    __shared__ float spy[Nn];
    __shared__ float spz[Nn];
    int t = threadIdx.x, w = t>>5, lane = t&31;
    int b = blockIdx.y;
    const float* xb = x + b*3*Nn;
    for (int e=t; e<Nn; e+=128){
        int se = e ^ ((e>>5)&31);
        spx[se] = xb[e]; spy[se] = xb[Nn+e]; spz[se] = xb[2*Nn+e];
    }
    __syncthreads();
    const unsigned INFU = 0x7F800000u;
    const float INFV = __uint_as_float(INFU);

    for (int i=0;i<4;i++){
        int q = blockIdx.x*16 + w*4 + i;
        int sq = q ^ ((q>>5)&31);
        float qx = spx[sq], qy = spy[sq], qz = spz[sq];
        float m1 = INFV, m2 = INFV; int a1 = 0, a2 = 0;
        unsigned long long mask = 0ULL;
        #pragma unroll 8
        for (int tt=0; tt<64; tt++){
            int j  = lane + (tt<<5);
            int sj = j ^ (tt & 31);
            float dx = spx[sj]-qx, dy = spy[sj]-qy, dz = spz[sj]-qz;
            float d2 = dx*dx + dy*dy + dz*dz;
            if (d2 < m1){ m2=m1; a2=a1; m1=d2; a1=j; }
            else if (d2 < m2){ m2=d2; a2=j; }
        }
        int myn = 0;
        for (int kk=0; kk<Kn; kk++){
            unsigned gm = __reduce_min_sync(0xffffffffu, __float_as_uint(m1));
            unsigned bm = __ballot_sync(0xffffffffu, __float_as_uint(m1)==gm);
            int L = __ffs(bm) - 1;
            int jst = __shfl_sync(0xffffffffu, a1, L);
            if (lane == kk) myn = jst;
            if (lane == L){
                mask |= 1ULL << (jst >> 5);       // mark extracted slot
                m1 = m2; a1 = a2; m2 = INFV;      // pop register cache
            }
            unsigned rs = __ballot_sync(0xffffffffu,
                          (lane==L) && (__float_as_uint(m1)==INFU));
            if (rs){
                unsigned long long msk = __shfl_sync(0xffffffffu, mask, L);
                int tt1 = lane, tt2 = lane + 32;
                int j1 = L + (tt1<<5), j2 = L + (tt2<<5);
                float v1 = INFV, v2 = INFV;
                if (!((msk >> tt1) & 1ULL)){
                    int s1i = j1 ^ (tt1 & 31);
                    float dx = spx[s1i]-qx, dy = spy[s1i]-qy, dz = spz[s1i]-qz;
                    v1 = dx*dx + dy*dy + dz*dz;
                }
                if (!((msk >> tt2) & 1ULL)){
                    int s2i = j2 ^ (tt2 & 31);
                    float dx = spx[s2i]-qx, dy = spy[s2i]-qy, dz = spz[s2i]-qz;
                    v2 = dx*dx + dy*dy + dz*dz;
                }
                float nv; int na;
                if (v1 <= v2){ nv = v1; na = j1; } else { nv = v2; na = j2; }
                unsigned r2 = __reduce_min_sync(0xffffffffu, __float_as_uint(nv));
                unsigned b2 = __ballot_sync(0xffffffffu, __float_as_uint(nv)==r2);
                int s2 = __ffs(b2) - 1;
                int na2 = __shfl_sync(0xffffffffu, na, s2);
                if (lane == L){ m1 = __uint_as_float(r2); a1 = na2; }
            }
        }
        if (lane < Kn) g_idx[(b*Nn + q)*Kn + lane] = myn;
    }
}

// ---------------- per-point: perm + agg + g fused into dnorm ----------------
__global__ void k_point(const float* __restrict__ x,
                        const float* __restrict__ kern,
                        const float* __restrict__ onepad){
    __shared__ int   sidx[2][Kn];
    __shared__ float sSelf[2][3];
    __shared__ __align__(16) float4 sR4[2][Kn];     // (rx,ry,rz,dist)
    __shared__ __align__(16) float sP[2][Kn][24];

    int t = threadIdx.x;
    int half = t >> 6, u = t & 63;
    int p = blockIdx.x*2 + half;
    int b = p >> 11, n = p & 2047;
    float* xrow = g_X + (size_t)p*XSTRIDE;

    if (u < Kn) sidx[half][u] = g_idx[p*Kn + u];
    if (u < 3)  sSelf[half][u] = x[b*3*Nn + u*Nn + n];
    __syncthreads();

    if (u < Kn){
        int j = sidx[half][u];
        float rx = x[b*3*Nn +        j] - sSelf[half][0];
        float ry = x[b*3*Nn +   Nn + j] - sSelf[half][1];
        float rz = x[b*3*Nn + 2*Nn + j] - sSelf[half][2];
        float d  = sqrtf(rx*rx + ry*ry + rz*rz + 1e-12f);
        sR4[half][u] = make_float4(rx, ry, rz, d);
    }
    // self feature row directly to g_X
    xrow[1440 + u] = g_Ft[p*Cin + u];
    __syncthreads();

    // raw perm = relu(rel @ kernals + one_padding)
    #pragma unroll
    for (int e=u; e<Kn*KSn; e+=64){
        int k = e/KSn, m = e - k*KSn;
        float4 r = sR4[half][k];
        float s = r.x*kern[m] + r.y*kern[KSn+m]
                + r.z*kern[2*KSn+m] + onepad[e];
        sP[half][k][m] = fmaxf(s, 0.f);
    }
    __syncthreads();

    // double normalization over k + threshold (column m=u), fused g-vector
    if (u < KSn){
        float s1 = 0.f;
        #pragma unroll
        for (int k=0;k<Kn;k++) s1 += sP[half][k][u];
        float inv1 = 1.f/(s1 + 1e-6f);
        float v[Kn]; float s2 = 0.f;
        #pragma unroll
        for (int k=0;k<Kn;k++){ float q = sP[half][k][u]*inv1; q = q*q; v[k] = q; s2 += q; }
        float inv2 = 1.f/(s2 + 1e-6f);
        float s3 = 0.f;
        float g3 = 0.f, g4 = 0.f, g5 = 0.f, g6 = 0.f;
        #pragma unroll
        for (int k=0;k<Kn;k++){
            float q = v[k]*inv2;
            q = (q > 0.1f) ? q : 0.f;
            sP[half][k][u] = q; s3 += q;
            float4 r = sR4[half][k];
            g3 += r.x*q; g4 += r.y*q; g5 += r.z*q; g6 += r.w*q;
        }
        float sx = sSelf[half][0]*s3;
        float sy = sSelf[half][1]*s3;
        float sz = sSelf[half][2]*s3;
        float4* gx = (float4*)(xrow + 1280 + u*8);
        gx[0] = make_float4(sx, sy, sz, g3);
        gx[1] = make_float4(g4, g5, g6, s3);
    }
    __syncthreads();

    // agg[c][m] = sum_k NF[k][c]*P[k][m]; thread u = channel c, all 20 m.
    {
        const int base = b*Nn;
        float acc[20];
        #pragma unroll
        for (int i=0;i<20;i++) acc[i] = 0.f;
        #pragma unroll
        for (int k=0;k<Kn;k++){
            float vv = g_Ft[(size_t)(base + sidx[half][k])*Cin + u];
            const float4* pr = (const float4*)sP[half][k];
            float4 q0 = pr[0], q1 = pr[1], q2 = pr[2], q3 = pr[3], q4 = pr[4];
            acc[0]+=vv*q0.x;  acc[1]+=vv*q0.y;  acc[2]+=vv*q0.z;  acc[3]+=vv*q0.w;
            acc[4]+=vv*q1.x;  acc[5]+=vv*q1.y;  acc[6]+=vv*q1.z;  acc[7]+=vv*q1.w;
            acc[8]+=vv*q2.x;  acc[9]+=vv*q2.y;  acc[10]+=vv*q2.z; acc[11]+=vv*q2.w;
            acc[12]+=vv*q3.x; acc[13]+=vv*q3.y; acc[14]+=vv*q3.z; acc[15]+=vv*q3.w;
            acc[16]+=vv*q4.x; acc[17]+=vv*q4.y; acc[18]+=vv*q4.z; acc[19]+=vv*q4.w;
        }
        #pragma unroll
        for (int m=0;m<20;m++)
            xrow[m*64 + u] = acc[m];
    }
}

// ---------------- GEMM (split-K=2, FFMA2, double-buffered smem) ----------------
// thread tile: 8 consecutive p-rows (4 packed pairs) x 4 o-columns
__global__ void __launch_bounds__(256) k_gemm(){
    __shared__ float As[2][16][132];
    __shared__ __align__(16) float Bs[2][16][64];
    int t = threadIdx.x;
    int p0 = blockIdx.x * 128;
    int h  = blockIdx.y;
    int k0 = h * XKH;
    int tx = t & 15, ty = t >> 4;
    int arow = t >> 2, aseg = t & 3;       // As loader mapping (rows 0..63 / +64)
    int bk   = t >> 4, bseg = t & 15;      // Bs loader mapping
    unsigned long long acc[4][4];
    #pragma unroll
    for (int i=0;i<4;i++)
        #pragma unroll
        for (int j=0;j<4;j++) acc[i][j] = 0ULL;

    const float* a0p = g_X + (size_t)(p0+arow)*XSTRIDE + aseg*4;
    const float* a1p = g_X + (size_t)(p0+64+arow)*XSTRIDE + aseg*4;
    const float* bp  = g_Wt + bk*64 + bseg*4;

    // preload tile 0 into buffer 0
    {
        float4 v0 = *(const float4*)(a0p + k0);
        float4 v1 = *(const float4*)(a1p + k0);
        float4 wv = *(const float4*)(bp + k0*64);
        As[0][aseg*4+0][arow] = v0.x; As[0][aseg*4+1][arow] = v0.y;
        As[0][aseg*4+2][arow] = v0.z; As[0][aseg*4+3][arow] = v0.w;
        As[0][aseg*4+0][64+arow] = v1.x; As[0][aseg*4+1][64+arow] = v1.y;
        As[0][aseg*4+2][64+arow] = v1.z; As[0][aseg*4+3][64+arow] = v1.w;
        *(float4*)&Bs[0][bk][bseg*4] = wv;
    }
    __syncthreads();

    #pragma unroll 1
    for (int it=0; it<47; it++){
        int cur = it & 1, nxt = cur ^ 1;
        int ktn = k0 + (it+1)*16;
        float4 v0, v1, wv;
        bool more = (it < 46);
        if (more){
            v0 = *(const float4*)(a0p + ktn);
            v1 = *(const float4*)(a1p + ktn);
            wv = *(const float4*)(bp + ktn*64);
        }
        #pragma unroll
        for (int k=0;k<16;k++){
            const float* ar = &As[cur][k][ty*8];
            unsigned long long a0 = *(const unsigned long long*)(ar+0);
            unsigned long long a1 = *(const unsigned long long*)(ar+2);
            unsigned long long a2 = *(const unsigned long long*)(ar+4);
            unsigned long long a3 = *(const unsigned long long*)(ar+6);
            float4 bv = *(const float4*)&Bs[cur][k][tx*4];
            unsigned long long b0,b1,b2,b3;
            asm("mov.b64 %0, {%1, %1};" : "=l"(b0) : "r"(__float_as_uint(bv.x)));
            asm("mov.b64 %0, {%1, %1};" : "=l"(b1) : "r"(__float_as_uint(bv.y)));
            asm("mov.b64 %0, {%1, %1};" : "=l"(b2) : "r"(__float_as_uint(bv.z)));
            asm("mov.b64 %0, {%1, %1};" : "=l"(b3) : "r"(__float_as_uint(bv.w)));
            FMA2(acc[0][0], a0, b0); FMA2(acc[0][1], a0, b1);
            FMA2(acc[0][2], a0, b2); FMA2(acc[0][3], a0, b3);
            FMA2(acc[1][0], a1, b0); FMA2(acc[1][1], a1, b1);
            FMA2(acc[1][2], a1, b2); FMA2(acc[1][3], a1, b3);
            FMA2(acc[2][0], a2, b0); FMA2(acc[2][1], a2, b1);
            FMA2(acc[2][2], a2, b2); FMA2(acc[2][3], a2, b3);
            FMA2(acc[3][0], a3, b0); FMA2(acc[3][1], a3, b1);
            FMA2(acc[3][2], a3, b2); FMA2(acc[3][3], a3, b3);
        }
        if (more){
            As[nxt][aseg*4+0][arow] = v0.x; As[nxt][aseg*4+1][arow] = v0.y;
            As[nxt][aseg*4+2][arow] = v0.z; As[nxt][aseg*4+3][arow] = v0.w;
            As[nxt][aseg*4+0][64+arow] = v1.x; As[nxt][aseg*4+1][64+arow] = v1.y;
            As[nxt][aseg*4+2][64+arow] = v1.z; As[nxt][aseg*4+3][64+arow] = v1.w;
            *(float4*)&Bs[nxt][bk][bseg*4] = wv;
            __syncthreads();
        }
    }
    float* dst = h ? g_o1b : g_o1a;
    #pragma unroll
    for (int j=0;j<4;j++){
        int o = tx*4 + j;
        float bb = h ? 0.f : g_bias[o];
        #pragma unroll
        for (int i=0;i<4;i++){
            float lo = __uint_as_float((unsigned)(acc[i][j] & 0xffffffffULL));
            float hi = __uint_as_float((unsigned)(acc[i][j] >> 32));
            *(float2*)&dst[o*NP + p0 + ty*8 + i*2] = make_float2(lo+bb, hi+bb);
        }
    }
}

// ---------------- BN statistics per channel (float4 reads) ----------------
__global__ void k_bnstat(const float* __restrict__ gamma,
                         const float* __restrict__ beta){
    int o = blockIdx.x, t = threadIdx.x;
    const float4* ra = (const float4*)(g_o1a + o*NP);
    const float4* rb = (const float4*)(g_o1b + o*NP);
    double s = 0.0, s2 = 0.0;
    for (int i=t; i<NP/4; i+=256){
        float4 va = ra[i], vb = rb[i];
        double v0 = (double)(va.x+vb.x), v1 = (double)(va.y+vb.y);
        double v2 = (double)(va.z+vb.z), v3 = (double)(va.w+vb.w);
        s += v0+v1+v2+v3;
        s2 += v0*v0 + v1*v1 + v2*v2 + v3*v3;
    }
    __shared__ double sh1[256], sh2[256];
    sh1[t] = s; sh2[t] = s2;
    __syncthreads();
    for (int off=128; off; off>>=1){
        if (t < off){ sh1[t] += sh1[t+off]; sh2[t] += sh2[t+off]; }
        __syncthreads();
    }
    if (t == 0){
        double mean = sh1[0] / (double)NP;
        double var  = sh2[0] / (double)NP - mean*mean;
        float sc = gamma[o] / sqrtf((float)var + 1e-5f);
        g_scale[o] = sc;
        g_shift[o] = beta[o] - (float)mean * sc;
    }
}

// ---------------- finalize: affine BN + layout [B,C,N] (float4) ----------------
__global__ void k_final(float* __restrict__ out){
    int e4 = blockIdx.x*blockDim.x + threadIdx.x;   // < 262144
    int base = e4 * 4;
    int n = base & 2047;
    int o = (base >> 11) & 63;
    int b = base >> 17;
    int idx = o*NP + b*Nn + n;
    float4 va = *(const float4*)(g_o1a + idx);
    float4 vb = *(const float4*)(g_o1b + idx);
    float sc = g_scale[o], sh = g_shift[o];
    float4 r;
    r.x = (va.x+vb.x)*sc + sh;
    r.y = (va.y+vb.y)*sc + sh;
    r.z = (va.z+vb.z)*sc + sh;
    r.w = (va.w+vb.w)*sc + sh;
    *(float4*)(out + base) = r;
}

// ---------------- launch ----------------
extern "C" void kernel_launch(void* const* d_in, const int* in_sizes, int n_in,
                              void* d_out, int out_size){
    (void)in_sizes; (void)n_in; (void)out_size;
    const float* x         = (const float*)d_in[0];
    const float* feature   = (const float*)d_in[1];
    const float* kernals   = (const float*)d_in[2];
    const float* one_pad   = (const float*)d_in[3];
    const float* mlp_w     = (const float*)d_in[4];
    const float* mlp_b     = (const float*)d_in[5];
    const float* conv_w    = (const float*)d_in[6];
    const float* conv_b    = (const float*)d_in[7];
    const float* mlp_out_w = (const float*)d_in[8];
    const float* mlp_out_b = (const float*)d_in[9];
    const float* bn_gamma  = (const float*)d_in[10];
    const float* bn_beta   = (const float*)d_in[11];
    float* out = (float*)d_out;

    k_transpose<<<dim3(Nn/32, Cin/32, Bn), dim3(32,8)>>>(feature);
    k_prepw<<<(XSTRIDE*Cout)/256, 256>>>(conv_w, mlp_w, mlp_b, mlp_out_w);
    k_prepb<<<1, 64>>>(conv_b, mlp_out_b);
    k_knn<<<dim3(Nn/16, Bn), 128>>>(x);
    k_point<<<NP/2, 128>>>(x, kernals, one_pad);
    k_gemm<<<dim3(NP/128, 2), 256>>>();
    k_bnstat<<<Cout, 256>>>(bn_gamma, bn_beta);
    k_final<<<(Bn*Cout*Nn)/1024, 256>>>(out);
}